// round 2
// baseline (speedup 1.0000x reference)
#include <cuda_runtime.h>
#include <cuda_bf16.h>

#define NHIT 30000
#define NEDGE 90000
#define NSP 30000
#define HD 128
#define NCLASS 5

// ---------------- device scratch (no allocations allowed) ----------------
__device__ float g_h[2][3][NHIT * HD];      // ping-pong hidden states per plane
__device__ float g_A[NHIT * HD];            // h @ W_msg1_top
__device__ float g_B[NHIT * HD];            // h @ W_msg1_bot
__device__ float g_mr[NHIT * HD];           // mean relu(A[dst]+B[src]+b1) per node
__device__ float g_agg[NHIT * HD];          // g_mr @ W_msg2 (+b2 masked)
__device__ float g_spsum[NSP * HD];         // sum of per-plane nexus means
__device__ float g_sp[NSP * HD];            // relu(spsum @ W_sp + b_sp)
__device__ float g_back[NHIT * HD];         // per-plane sp->hit mean

__device__ int g_deg[3][NHIT];              // planar in-degree (dst)
__device__ int g_cf[3][NSP];                // nexus fwd counts (per spacepoint)
__device__ int g_cb[3][NHIT];               // nexus back counts (per hit)
__device__ int g_offE[3][NHIT + 1];
__device__ int g_offF[3][NSP + 1];
__device__ int g_offB[3][NHIT + 1];
__device__ int g_csrE[3][NEDGE];            // src per edge, bucketed by dst
__device__ int g_csrF[3][NSP];              // hit idx bucketed by sp idx
__device__ int g_csrB[3][NSP];              // sp idx bucketed by hit idx
__device__ int g_cur[NHIT];                 // shared cursor buffer

enum { EPI_PLAIN = 0, EPI_RELU = 1, EPI_RESRELU = 2, EPI_MASKBIAS = 3 };

// ---------------- CSR build ----------------
__global__ void zero_counts() {
    int i = blockIdx.x * blockDim.x + threadIdx.x;
    if (i < NHIT) {
        #pragma unroll
        for (int p = 0; p < 3; p++) { g_deg[p][i] = 0; g_cb[p][i] = 0; }
    }
    if (i < NSP) {
        #pragma unroll
        for (int p = 0; p < 3; p++) g_cf[p][i] = 0;
    }
}

__global__ void count_edge(const int* __restrict__ edge, int p) {
    int e = blockIdx.x * blockDim.x + threadIdx.x;
    if (e >= NEDGE) return;
    atomicAdd(&g_deg[p][edge[NEDGE + e]], 1);
}

__global__ void count_nx(const int* __restrict__ nx, int p) {
    int i = blockIdx.x * blockDim.x + threadIdx.x;
    if (i >= NSP) return;
    atomicAdd(&g_cf[p][nx[NSP + i]], 1);
    atomicAdd(&g_cb[p][nx[i]], 1);
}

// single-block exclusive scan (n <= 30000, blockDim = 1024)
__global__ void scan_excl(int sel, int p) {
    const int* in; int* out; int n;
    if (sel == 0)      { in = g_deg[p]; out = g_offE[p]; n = NHIT; }
    else if (sel == 1) { in = g_cf[p];  out = g_offF[p]; n = NSP; }
    else               { in = g_cb[p];  out = g_offB[p]; n = NHIT; }
    __shared__ int wsum[32];
    __shared__ int carry;
    int tid = threadIdx.x;
    if (tid == 0) carry = 0;
    __syncthreads();
    for (int base = 0; base < n; base += 1024) {
        int i = base + tid;
        int v = (i < n) ? in[i] : 0;
        int x = v;
        #pragma unroll
        for (int d = 1; d < 32; d <<= 1) {
            int y = __shfl_up_sync(0xffffffffu, x, d);
            if ((tid & 31) >= d) x += y;
        }
        if ((tid & 31) == 31) wsum[tid >> 5] = x;
        __syncthreads();
        if (tid < 32) {
            int s = wsum[tid];
            #pragma unroll
            for (int d = 1; d < 32; d <<= 1) {
                int y = __shfl_up_sync(0xffffffffu, s, d);
                if (tid >= d) s += y;
            }
            wsum[tid] = s;
        }
        __syncthreads();
        int woff = (tid >= 32) ? wsum[(tid >> 5) - 1] : 0;
        int incl = carry + woff + x;
        if (i < n) out[i] = incl - v;
        __syncthreads();
        if (tid == 1023) carry = incl;
        __syncthreads();
    }
    if (tid == 0) out[n] = carry;
}

__global__ void init_cursor(int sel, int p) {
    int i = blockIdx.x * blockDim.x + threadIdx.x;
    int n = (sel == 1) ? NSP : NHIT;
    if (i >= n) return;
    g_cur[i] = (sel == 0) ? g_offE[p][i] : (sel == 1) ? g_offF[p][i] : g_offB[p][i];
}

__global__ void fill_edge(const int* __restrict__ edge, int p) {
    int e = blockIdx.x * blockDim.x + threadIdx.x;
    if (e >= NEDGE) return;
    int dst = edge[NEDGE + e];
    int pos = atomicAdd(&g_cur[dst], 1);
    g_csrE[p][pos] = edge[e];
}

__global__ void fill_f(const int* __restrict__ nx, int p) {
    int i = blockIdx.x * blockDim.x + threadIdx.x;
    if (i >= NSP) return;
    int s = nx[NSP + i];
    int pos = atomicAdd(&g_cur[s], 1);
    g_csrF[p][pos] = nx[i];
}

__global__ void fill_b(const int* __restrict__ nx, int p) {
    int i = blockIdx.x * blockDim.x + threadIdx.x;
    if (i >= NSP) return;
    int n0 = nx[i];
    int pos = atomicAdd(&g_cur[n0], 1);
    g_csrB[p][pos] = nx[NSP + i];
}

// ---------------- encoder ----------------
__global__ void encoder_k(const float* __restrict__ x, const float* __restrict__ W,
                          const float* __restrict__ b, float* __restrict__ h) {
    int idx = blockIdx.x * blockDim.x + threadIdx.x;
    if (idx >= NHIT * HD) return;
    int n = idx >> 7, j = idx & 127;
    float acc = b[j];
    #pragma unroll
    for (int k = 0; k < 4; k++) acc = fmaf(x[n * 4 + k], W[k * HD + j], acc);
    h[idx] = fmaxf(acc, 0.f);
}

// ---------------- generic tiled SGEMM: out[M,128] = [A0|A1][M,K] @ W[K,128] ----------------
__global__ __launch_bounds__(256) void gemm128(
    const float* __restrict__ A0, const float* __restrict__ A1,
    const float* __restrict__ W, const float* __restrict__ bias,
    const float* __restrict__ resid, const int* __restrict__ mask,
    float* __restrict__ out, int M, int K, int epi)
{
    __shared__ float As[16][128];
    __shared__ float Ws[16][128];
    int tid = threadIdx.x;
    int tx = tid & 15, ty = tid >> 4;
    int row0 = blockIdx.x * 128;
    float acc[8][8];
    #pragma unroll
    for (int i = 0; i < 8; i++)
        #pragma unroll
        for (int j = 0; j < 8; j++) acc[i][j] = 0.f;

    for (int kc = 0; kc < K; kc += 16) {
        const float* Ap = (kc < 128) ? A0 : A1;
        int kcl = (kc < 128) ? kc : kc - 128;
        #pragma unroll
        for (int l = 0; l < 2; l++) {
            int f = tid + l * 256;       // 0..511
            int r = f >> 2;              // 0..127
            int c4 = (f & 3) * 4;        // 0,4,8,12
            float4 v = make_float4(0.f, 0.f, 0.f, 0.f);
            int row = row0 + r;
            if (row < M) v = *reinterpret_cast<const float4*>(&Ap[row * 128 + kcl + c4]);
            As[c4 + 0][r] = v.x; As[c4 + 1][r] = v.y;
            As[c4 + 2][r] = v.z; As[c4 + 3][r] = v.w;
        }
        #pragma unroll
        for (int l = 0; l < 2; l++) {
            int f = tid + l * 256;
            int kr = f >> 5;             // 0..15
            int c4 = (f & 31) * 4;       // 0..124
            *reinterpret_cast<float4*>(&Ws[kr][c4]) =
                *reinterpret_cast<const float4*>(&W[(kc + kr) * 128 + c4]);
        }
        __syncthreads();
        #pragma unroll
        for (int k = 0; k < 16; k++) {
            float4 a0 = *reinterpret_cast<const float4*>(&As[k][ty * 8]);
            float4 a1 = *reinterpret_cast<const float4*>(&As[k][ty * 8 + 4]);
            float4 b0 = *reinterpret_cast<const float4*>(&Ws[k][tx * 8]);
            float4 b1 = *reinterpret_cast<const float4*>(&Ws[k][tx * 8 + 4]);
            float a[8] = {a0.x, a0.y, a0.z, a0.w, a1.x, a1.y, a1.z, a1.w};
            float b[8] = {b0.x, b0.y, b0.z, b0.w, b1.x, b1.y, b1.z, b1.w};
            #pragma unroll
            for (int i = 0; i < 8; i++)
                #pragma unroll
                for (int j = 0; j < 8; j++) acc[i][j] = fmaf(a[i], b[j], acc[i][j]);
        }
        __syncthreads();
    }

    float bv[8];
    if (epi != EPI_PLAIN) {
        #pragma unroll
        for (int j = 0; j < 8; j++) bv[j] = bias[tx * 8 + j];
    }
    #pragma unroll
    for (int i = 0; i < 8; i++) {
        int row = row0 + ty * 8 + i;
        if (row >= M) continue;
        float o[8];
        if (epi == EPI_PLAIN) {
            #pragma unroll
            for (int j = 0; j < 8; j++) o[j] = acc[i][j];
        } else if (epi == EPI_RELU) {
            #pragma unroll
            for (int j = 0; j < 8; j++) o[j] = fmaxf(acc[i][j] + bv[j], 0.f);
        } else if (epi == EPI_RESRELU) {
            #pragma unroll
            for (int j = 0; j < 8; j++)
                o[j] = resid[row * 128 + tx * 8 + j] + fmaxf(acc[i][j] + bv[j], 0.f);
        } else { // EPI_MASKBIAS
            bool m = mask[row] > 0;
            #pragma unroll
            for (int j = 0; j < 8; j++) o[j] = m ? (acc[i][j] + bv[j]) : 0.f;
        }
        *reinterpret_cast<float4*>(&out[row * 128 + tx * 8]) =
            make_float4(o[0], o[1], o[2], o[3]);
        *reinterpret_cast<float4*>(&out[row * 128 + tx * 8 + 4]) =
            make_float4(o[4], o[5], o[6], o[7]);
    }
}

// ---------------- planar edge aggregation (warp per node, CSR, no atomics) ----------------
__global__ void planar_agg(const float* __restrict__ b1, int p) {
    int warp = (blockIdx.x * blockDim.x + threadIdx.x) >> 5;
    if (warp >= NHIT) return;
    int lane = threadIdx.x & 31;
    int n = warp;
    float4 a = *reinterpret_cast<const float4*>(&g_A[n * HD + lane * 4]);
    float4 bb = *reinterpret_cast<const float4*>(&b1[lane * 4]);
    int s = g_offE[p][n], e = g_offE[p][n + 1];
    float4 acc = make_float4(0.f, 0.f, 0.f, 0.f);
    for (int i = s; i < e; i++) {
        int src = g_csrE[p][i];
        float4 b = *reinterpret_cast<const float4*>(&g_B[src * HD + lane * 4]);
        acc.x += fmaxf(a.x + b.x + bb.x, 0.f);
        acc.y += fmaxf(a.y + b.y + bb.y, 0.f);
        acc.z += fmaxf(a.z + b.z + bb.z, 0.f);
        acc.w += fmaxf(a.w + b.w + bb.w, 0.f);
    }
    float inv = (e > s) ? 1.f / (float)(e - s) : 0.f;
    *reinterpret_cast<float4*>(&g_mr[n * HD + lane * 4]) =
        make_float4(acc.x * inv, acc.y * inv, acc.z * inv, acc.w * inv);
}

// ---------------- nexus forward: spsum[s] = sum_p mean over hits of h_p ----------------
__global__ void nexus_fwd(const float* __restrict__ h0, const float* __restrict__ h1,
                          const float* __restrict__ h2) {
    int warp = (blockIdx.x * blockDim.x + threadIdx.x) >> 5;
    if (warp >= NSP) return;
    int lane = threadIdx.x & 31;
    int s = warp;
    const float* hs[3] = {h0, h1, h2};
    float4 tot = make_float4(0.f, 0.f, 0.f, 0.f);
    #pragma unroll
    for (int p = 0; p < 3; p++) {
        int st = g_offF[p][s], en = g_offF[p][s + 1];
        float4 acc = make_float4(0.f, 0.f, 0.f, 0.f);
        for (int i = st; i < en; i++) {
            int hit = g_csrF[p][i];
            float4 v = *reinterpret_cast<const float4*>(&hs[p][hit * HD + lane * 4]);
            acc.x += v.x; acc.y += v.y; acc.z += v.z; acc.w += v.w;
        }
        if (en > st) {
            float inv = 1.f / (float)(en - st);
            tot.x += acc.x * inv; tot.y += acc.y * inv;
            tot.z += acc.z * inv; tot.w += acc.w * inv;
        }
    }
    *reinterpret_cast<float4*>(&g_spsum[s * HD + lane * 4]) = tot;
}

// ---------------- nexus backward: back[n] = mean over sps of g_sp ----------------
__global__ void nexus_back(int p) {
    int warp = (blockIdx.x * blockDim.x + threadIdx.x) >> 5;
    if (warp >= NHIT) return;
    int lane = threadIdx.x & 31;
    int n = warp;
    int st = g_offB[p][n], en = g_offB[p][n + 1];
    float4 acc = make_float4(0.f, 0.f, 0.f, 0.f);
    for (int i = st; i < en; i++) {
        int spi = g_csrB[p][i];
        float4 v = *reinterpret_cast<const float4*>(&g_sp[spi * HD + lane * 4]);
        acc.x += v.x; acc.y += v.y; acc.z += v.z; acc.w += v.w;
    }
    float inv = (en > st) ? 1.f / (float)(en - st) : 0.f;
    *reinterpret_cast<float4*>(&g_back[n * HD + lane * 4]) =
        make_float4(acc.x * inv, acc.y * inv, acc.z * inv, acc.w * inv);
}

// ---------------- decoder: out = h @ W_sem + b_sem (warp per row) ----------------
__global__ void decoder_k(const float* __restrict__ h, const float* __restrict__ Wsem,
                          const float* __restrict__ bsem, float* __restrict__ out) {
    int warp = (blockIdx.x * blockDim.x + threadIdx.x) >> 5;
    if (warp >= NHIT) return;
    int lane = threadIdx.x & 31;
    int n = warp;
    float hv[4];
    #pragma unroll
    for (int t = 0; t < 4; t++) hv[t] = h[n * HD + lane + t * 32];
    #pragma unroll
    for (int c = 0; c < NCLASS; c++) {
        float s = 0.f;
        #pragma unroll
        for (int t = 0; t < 4; t++) s = fmaf(hv[t], Wsem[(lane + t * 32) * NCLASS + c], s);
        #pragma unroll
        for (int d = 16; d > 0; d >>= 1) s += __shfl_down_sync(0xffffffffu, s, d);
        if (lane == 0) out[n * NCLASS + c] = s + bsem[c];
    }
}

// ---------------- host ----------------
extern "C" void kernel_launch(void* const* d_in, const int* in_sizes, int n_in,
                              void* d_out, int out_size) {
    // layout detection: grouped (x,edge,nexus per plane) vs signature order
    int xi[3], ei[3], ni[3];
    if (in_sizes[1] == 2 * NEDGE) {
        for (int p = 0; p < 3; p++) { xi[p] = 3 * p; ei[p] = 3 * p + 1; ni[p] = 3 * p + 2; }
    } else {
        for (int p = 0; p < 3; p++) { xi[p] = p; ei[p] = 3 + p; ni[p] = 6 + p; }
    }
    const float* x[3]; const int* edge[3]; const int* nexus[3];
    for (int p = 0; p < 3; p++) {
        x[p] = (const float*)d_in[xi[p]];
        edge[p] = (const int*)d_in[ei[p]];
        nexus[p] = (const int*)d_in[ni[p]];
    }
    const float* W_enc  = (const float*)d_in[9];
    const float* b_enc  = (const float*)d_in[10];
    const float* W_msg1 = (const float*)d_in[11];
    const float* b_msg1 = (const float*)d_in[12];
    const float* W_msg2 = (const float*)d_in[13];
    const float* b_msg2 = (const float*)d_in[14];
    const float* W_upd  = (const float*)d_in[15];
    const float* b_upd  = (const float*)d_in[16];
    const float* W_sp   = (const float*)d_in[17];
    const float* b_sp   = (const float*)d_in[18];
    const float* W_nx   = (const float*)d_in[19];
    const float* b_nx   = (const float*)d_in[20];
    const float* W_sem  = (const float*)d_in[21];
    const float* b_sem  = (const float*)d_in[22];

    float *ph, *pA, *pB, *pmr, *pagg, *pspsum, *psp, *pback;
    int* pdeg;
    cudaGetSymbolAddress((void**)&ph, g_h);
    cudaGetSymbolAddress((void**)&pA, g_A);
    cudaGetSymbolAddress((void**)&pB, g_B);
    cudaGetSymbolAddress((void**)&pmr, g_mr);
    cudaGetSymbolAddress((void**)&pagg, g_agg);
    cudaGetSymbolAddress((void**)&pspsum, g_spsum);
    cudaGetSymbolAddress((void**)&psp, g_sp);
    cudaGetSymbolAddress((void**)&pback, g_back);
    cudaGetSymbolAddress((void**)&pdeg, g_deg);

    auto HB = [&](int b, int p) { return ph + ((size_t)(b * 3 + p)) * NHIT * HD; };

    const int T = 256;
    dim3 gG((NHIT + 127) / 128);   // 235 blocks for GEMM
    int gWarp = (NHIT * 32 + T - 1) / T;  // warp-per-node kernels

    // --- CSR build (per call; edges are loop-invariant) ---
    zero_counts<<<(NHIT + T - 1) / T, T>>>();
    for (int p = 0; p < 3; p++) count_edge<<<(NEDGE + T - 1) / T, T>>>(edge[p], p);
    for (int p = 0; p < 3; p++) count_nx<<<(NSP + T - 1) / T, T>>>(nexus[p], p);
    for (int p = 0; p < 3; p++)
        for (int sel = 0; sel < 3; sel++) scan_excl<<<1, 1024>>>(sel, p);
    for (int p = 0; p < 3; p++) {
        init_cursor<<<(NHIT + T - 1) / T, T>>>(0, p);
        fill_edge<<<(NEDGE + T - 1) / T, T>>>(edge[p], p);
        init_cursor<<<(NSP + T - 1) / T, T>>>(1, p);
        fill_f<<<(NSP + T - 1) / T, T>>>(nexus[p], p);
        init_cursor<<<(NHIT + T - 1) / T, T>>>(2, p);
        fill_b<<<(NSP + T - 1) / T, T>>>(nexus[p], p);
    }

    // --- encoder ---
    for (int p = 0; p < 3; p++)
        encoder_k<<<(NHIT * HD + T - 1) / T, T>>>(x[p], W_enc, b_enc, HB(0, p));

    const int cur = 0;
    for (int it = 0; it < 3; it++) {
        // planar convolution per plane
        for (int p = 0; p < 3; p++) {
            gemm128<<<gG, T>>>(HB(cur, p), nullptr, W_msg1, nullptr, nullptr, nullptr,
                               pA, NHIT, 128, EPI_PLAIN);
            gemm128<<<gG, T>>>(HB(cur, p), nullptr, W_msg1 + 128 * 128, nullptr, nullptr,
                               nullptr, pB, NHIT, 128, EPI_PLAIN);
            planar_agg<<<gWarp, T>>>(b_msg1, p);
            gemm128<<<gG, T>>>(pmr, nullptr, W_msg2, b_msg2, nullptr, pdeg + p * NHIT,
                               pagg, NHIT, 128, EPI_MASKBIAS);
            gemm128<<<gG, T>>>(HB(cur, p), pagg, W_upd, b_upd, HB(cur, p), nullptr,
                               HB(1 - cur, p), NHIT, 256, EPI_RESRELU);
        }
        // nexus convolution
        nexus_fwd<<<gWarp, T>>>(HB(1 - cur, 0), HB(1 - cur, 1), HB(1 - cur, 2));
        gemm128<<<gG, T>>>(pspsum, nullptr, W_sp, b_sp, nullptr, nullptr,
                           psp, NSP, 128, EPI_RELU);
        for (int p = 0; p < 3; p++) {
            nexus_back<<<gWarp, T>>>(p);
            gemm128<<<gG, T>>>(HB(1 - cur, p), pback, W_nx, b_nx, HB(1 - cur, p), nullptr,
                               HB(cur, p), NHIT, 256, EPI_RESRELU);
        }
    }

    // --- decoder ---
    for (int p = 0; p < 3; p++)
        decoder_k<<<gWarp, T>>>(HB(0, p), W_sem, b_sem,
                                ((float*)d_out) + (size_t)p * NHIT * NCLASS);
}

// round 4
// speedup vs baseline: 2.1777x; 2.1777x over previous
#include <cuda_runtime.h>
#include <cuda_bf16.h>
#include <cstdint>

#define NHIT 30000
#define NEDGE 90000
#define NSP 30000
#define HD 128
#define NCLASS 5

// ---------------- device scratch (no allocations allowed) ----------------
__device__ float g_h[2][3][NHIT * HD];
__device__ float g_A[NHIT * HD];
__device__ float g_B[NHIT * HD];
__device__ float g_mr[NHIT * HD];
__device__ float g_agg[NHIT * HD];
__device__ float g_spsum[NSP * HD];
__device__ float g_sp[NSP * HD];
__device__ float g_back[NHIT * HD];

// prepped weights: 8 chunks x {hi,lo} x 2 k-stages x (128n x 64k bf16 = 16KB, swizzled)
__device__ uint4 g_wbuf[8][2][2][1024];

__device__ int g_deg[3][NHIT];
__device__ int g_cf[3][NSP];
__device__ int g_cb[3][NHIT];
__device__ int g_offE[3][NHIT + 1];
__device__ int g_offF[3][NSP + 1];
__device__ int g_offB[3][NHIT + 1];
__device__ int g_csrE[3][NEDGE];
__device__ int g_csrF[3][NSP];
__device__ int g_csrB[3][NSP];
__device__ int g_curE[3][NHIT];
__device__ int g_curF[3][NSP];
__device__ int g_curB[3][NHIT];

enum { EPI_PLAIN = 0, EPI_RELU = 1, EPI_RESRELU = 2, EPI_MASKBIAS = 3 };

// ---------------- helpers ----------------
__device__ __forceinline__ uint32_t s2u(const void* p) {
    return (uint32_t)__cvta_generic_to_shared(p);
}
__device__ __forceinline__ uint32_t pack2(float a, float b) {
    __nv_bfloat162 t = __floats2bfloat162_rn(a, b);
    return *reinterpret_cast<uint32_t*>(&t);
}
__device__ __forceinline__ float lopart(float v) {
    __nv_bfloat16 h = __float2bfloat16(v);
    return v - __bfloat162float(h);
}
// swizzled byte offset within a [128 rows x 64 k] bf16 tile (128B rows)
__device__ __forceinline__ uint32_t swz(int row, int k) {
    return (uint32_t)(row * 128 + ((((k >> 3) ^ row) & 7) << 4) + (k & 7) * 2);
}
__device__ __forceinline__ void ldsm4(uint32_t* r, uint32_t addr) {
    asm volatile("ldmatrix.sync.aligned.m8n8.x4.shared.b16 {%0,%1,%2,%3}, [%4];"
                 : "=r"(r[0]), "=r"(r[1]), "=r"(r[2]), "=r"(r[3]) : "r"(addr));
}
__device__ __forceinline__ void mma16816(float* c, const uint32_t* a, uint32_t b0, uint32_t b1) {
    asm volatile(
        "mma.sync.aligned.m16n8k16.row.col.f32.bf16.bf16.f32 "
        "{%0,%1,%2,%3}, {%4,%5,%6,%7}, {%8,%9}, {%0,%1,%2,%3};"
        : "+f"(c[0]), "+f"(c[1]), "+f"(c[2]), "+f"(c[3])
        : "r"(a[0]), "r"(a[1]), "r"(a[2]), "r"(a[3]), "r"(b0), "r"(b1));
}

// smem tile offsets (dynamic smem, 64KB)
#define SM_AHI 0
#define SM_ALO 16384
#define SM_BHI 32768
#define SM_BLO 49152
#define SM_TOTAL 65536

// ---------------- weight prep: transpose + hi/lo bf16 + swizzle ----------------
__global__ void prep_w(const float* w0, const float* w1, const float* w2,
                       const float* w3, const float* w4, const float* w5,
                       const float* w6, const float* w7) {
    int id = blockIdx.x * blockDim.x + threadIdx.x;   // 65536 total
    int c = id >> 13;
    int rem = id & 8191;
    int s = rem >> 12;
    int rem2 = rem & 4095;
    int n = rem2 >> 5;
    int kp = (rem2 & 31) * 2;
    const float* Wc = (c == 0) ? w0 : (c == 1) ? w1 : (c == 2) ? w2 : (c == 3) ? w3
                    : (c == 4) ? w4 : (c == 5) ? w5 : (c == 6) ? w6 : w7;
    float v0 = Wc[(s * 64 + kp) * 128 + n];
    float v1 = Wc[(s * 64 + kp + 1) * 128 + n];
    uint32_t o = swz(n, kp);
    *reinterpret_cast<uint32_t*>((char*)&g_wbuf[c][0][s][0] + o) = pack2(v0, v1);
    *reinterpret_cast<uint32_t*>((char*)&g_wbuf[c][1][s][0] + o) = pack2(lopart(v0), lopart(v1));
}

// ---------------- HMMA split-bf16 SGEMM: out[M,128] = [A0|A1][M,K] @ Wchunks ----------------
__global__ __launch_bounds__(256, 2) void gemm_mma(
    const float* __restrict__ A0, const float* __restrict__ A1,
    int wc0, int nchunks,
    const float* __restrict__ bias, const float* __restrict__ resid,
    const int* __restrict__ mask, float* __restrict__ out, int M, int epi)
{
    extern __shared__ char smem[];
    uint32_t sb = s2u(smem);
    int tid = threadIdx.x;
    int wid = tid >> 5, lane = tid & 31;
    int mwarp = wid & 3, nwarp = wid >> 2;   // warp tile: 32 rows x 64 cols
    int row0 = blockIdx.x * 128;

    float C[2][8][4];
    #pragma unroll
    for (int mt = 0; mt < 2; mt++)
        #pragma unroll
        for (int nt = 0; nt < 8; nt++)
            #pragma unroll
            for (int q = 0; q < 4; q++) C[mt][nt][q] = 0.f;

    // per-lane ldmatrix address components
    int a_row_in16 = (lane & 7) + ((lane >> 3) & 1) * 8;   // A: row within 16
    int a_kb = (lane >> 4) & 1;                             // A: k half (0/8)
    int b_row_in16 = (lane & 7) + ((lane >> 4) & 1) * 8;   // B: n within 16
    int b_kb = (lane >> 3) & 1;                             // B: k half

    for (int ch = 0; ch < nchunks; ch++) {
        const float* Ap = ch ? A1 : A0;
        for (int s = 0; s < 2; s++) {
            // --- stage A [128 x 64] fp32 -> hi/lo bf16 swizzled ---
            #pragma unroll
            for (int l = 0; l < 8; l++) {
                int i = l * 256 + tid;
                int r = i >> 4, c4 = (i & 15) * 4;
                float4 v = make_float4(0.f, 0.f, 0.f, 0.f);
                int row = row0 + r;
                if (row < M)
                    v = *reinterpret_cast<const float4*>(&Ap[(size_t)row * 128 + s * 64 + c4]);
                uint32_t o = swz(r, c4);
                *reinterpret_cast<uint2*>(smem + SM_AHI + o) =
                    make_uint2(pack2(v.x, v.y), pack2(v.z, v.w));
                *reinterpret_cast<uint2*>(smem + SM_ALO + o) =
                    make_uint2(pack2(lopart(v.x), lopart(v.y)), pack2(lopart(v.z), lopart(v.w)));
            }
            // --- stage B: plain copy of pre-swizzled weights ---
            const uint4* bh = &g_wbuf[wc0 + ch][0][s][0];
            const uint4* bl = &g_wbuf[wc0 + ch][1][s][0];
            #pragma unroll
            for (int l = 0; l < 4; l++) {
                int i = l * 256 + tid;
                *reinterpret_cast<uint4*>(smem + SM_BHI + i * 16) = bh[i];
                *reinterpret_cast<uint4*>(smem + SM_BLO + i * 16) = bl[i];
            }
            __syncthreads();

            #pragma unroll
            for (int k16 = 0; k16 < 4; k16++) {
                // A fragments (2 m-tiles, hi+lo)
                uint32_t ahi[2][4], alo[2][4];
                #pragma unroll
                for (int mt = 0; mt < 2; mt++) {
                    int row = mwarp * 32 + mt * 16 + a_row_in16;
                    uint32_t o = (uint32_t)(row * 128 +
                        ((((k16 * 2 + a_kb) ^ row) & 7) << 4));
                    ldsm4(ahi[mt], sb + SM_AHI + o);
                    ldsm4(alo[mt], sb + SM_ALO + o);
                }
                // B fragments in n-tile pairs
                #pragma unroll
                for (int ntp = 0; ntp < 4; ntp++) {
                    int nrow = nwarp * 64 + ntp * 16 + b_row_in16;
                    uint32_t o = (uint32_t)(nrow * 128 +
                        ((((k16 * 2 + b_kb) ^ nrow) & 7) << 4));
                    uint32_t bhi[4], blo[4];
                    ldsm4(bhi, sb + SM_BHI + o);
                    ldsm4(blo, sb + SM_BLO + o);
                    #pragma unroll
                    for (int half = 0; half < 2; half++) {
                        int nt = ntp * 2 + half;
                        #pragma unroll
                        for (int mt = 0; mt < 2; mt++) {
                            mma16816(C[mt][nt], ahi[mt], bhi[half * 2], bhi[half * 2 + 1]);
                            mma16816(C[mt][nt], ahi[mt], blo[half * 2], blo[half * 2 + 1]);
                            mma16816(C[mt][nt], alo[mt], bhi[half * 2], bhi[half * 2 + 1]);
                        }
                    }
                }
            }
            __syncthreads();
        }
    }

    // ---------------- epilogue ----------------
    int qrow = lane >> 2;
    int qcol = (lane & 3) * 2;
    #pragma unroll
    for (int mt = 0; mt < 2; mt++) {
        #pragma unroll
        for (int half = 0; half < 2; half++) {
            int row = row0 + mwarp * 32 + mt * 16 + qrow + half * 8;
            if (row >= M) continue;
            bool mk = (epi == EPI_MASKBIAS) ? (mask[row] > 0) : false;
            #pragma unroll
            for (int nt = 0; nt < 8; nt++) {
                int col = nwarp * 64 + nt * 8 + qcol;
                float v0 = C[mt][nt][half * 2 + 0];
                float v1 = C[mt][nt][half * 2 + 1];
                float o0, o1;
                if (epi == EPI_PLAIN) { o0 = v0; o1 = v1; }
                else if (epi == EPI_RELU) {
                    o0 = fmaxf(v0 + bias[col], 0.f);
                    o1 = fmaxf(v1 + bias[col + 1], 0.f);
                } else if (epi == EPI_RESRELU) {
                    float2 rr = *reinterpret_cast<const float2*>(&resid[(size_t)row * 128 + col]);
                    o0 = rr.x + fmaxf(v0 + bias[col], 0.f);
                    o1 = rr.y + fmaxf(v1 + bias[col + 1], 0.f);
                } else {
                    o0 = mk ? (v0 + bias[col]) : 0.f;
                    o1 = mk ? (v1 + bias[col + 1]) : 0.f;
                }
                *reinterpret_cast<float2*>(&out[(size_t)row * 128 + col]) = make_float2(o0, o1);
            }
        }
    }
}

// ---------------- CSR build ----------------
__global__ void zero_counts() {
    int i = blockIdx.x * blockDim.x + threadIdx.x;
    if (i < NHIT) {
        #pragma unroll
        for (int p = 0; p < 3; p++) { g_deg[p][i] = 0; g_cb[p][i] = 0; }
    }
    if (i < NSP) {
        #pragma unroll
        for (int p = 0; p < 3; p++) g_cf[p][i] = 0;
    }
}

__global__ void count_all(const int* __restrict__ e0, const int* __restrict__ e1,
                          const int* __restrict__ e2, const int* __restrict__ n0,
                          const int* __restrict__ n1, const int* __restrict__ n2) {
    int p = blockIdx.y;
    const int* e = (p == 0) ? e0 : (p == 1) ? e1 : e2;
    const int* nx = (p == 0) ? n0 : (p == 1) ? n1 : n2;
    int i = blockIdx.x * blockDim.x + threadIdx.x;
    if (i < NEDGE) atomicAdd(&g_deg[p][e[NEDGE + i]], 1);
    if (i < NSP) {
        atomicAdd(&g_cf[p][nx[NSP + i]], 1);
        atomicAdd(&g_cb[p][nx[i]], 1);
    }
}

__global__ void scan_excl_all() {
    int sel = blockIdx.x / 3, p = blockIdx.x % 3;
    const int* in; int* out; int* cur; int n;
    if (sel == 0)      { in = g_deg[p]; out = g_offE[p]; cur = g_curE[p]; n = NHIT; }
    else if (sel == 1) { in = g_cf[p];  out = g_offF[p]; cur = g_curF[p]; n = NSP; }
    else               { in = g_cb[p];  out = g_offB[p]; cur = g_curB[p]; n = NHIT; }
    __shared__ int wsum[32];
    __shared__ int carry;
    int tid = threadIdx.x;
    if (tid == 0) carry = 0;
    __syncthreads();
    for (int base = 0; base < n; base += 1024) {
        int i = base + tid;
        int v = (i < n) ? in[i] : 0;
        int x = v;
        #pragma unroll
        for (int d = 1; d < 32; d <<= 1) {
            int y = __shfl_up_sync(0xffffffffu, x, d);
            if ((tid & 31) >= d) x += y;
        }
        if ((tid & 31) == 31) wsum[tid >> 5] = x;
        __syncthreads();
        if (tid < 32) {
            int s = wsum[tid];
            #pragma unroll
            for (int d = 1; d < 32; d <<= 1) {
                int y = __shfl_up_sync(0xffffffffu, s, d);
                if (tid >= d) s += y;
            }
            wsum[tid] = s;
        }
        __syncthreads();
        int woff = (tid >= 32) ? wsum[(tid >> 5) - 1] : 0;
        int incl = carry + woff + x;
        if (i < n) { out[i] = incl - v; cur[i] = incl - v; }
        __syncthreads();
        if (tid == 1023) carry = incl;
        __syncthreads();
    }
    if (tid == 0) out[n] = carry;
}

__global__ void fill_all(const int* __restrict__ e0, const int* __restrict__ e1,
                         const int* __restrict__ e2, const int* __restrict__ n0,
                         const int* __restrict__ n1, const int* __restrict__ n2) {
    int p = blockIdx.y;
    const int* e = (p == 0) ? e0 : (p == 1) ? e1 : e2;
    const int* nx = (p == 0) ? n0 : (p == 1) ? n1 : n2;
    int i = blockIdx.x * blockDim.x + threadIdx.x;
    if (i < NEDGE) {
        int dst = e[NEDGE + i];
        g_csrE[p][atomicAdd(&g_curE[p][dst], 1)] = e[i];
    }
    if (i < NSP) {
        int s = nx[NSP + i];
        g_csrF[p][atomicAdd(&g_curF[p][s], 1)] = nx[i];
        int h = nx[i];
        g_csrB[p][atomicAdd(&g_curB[p][h], 1)] = nx[NSP + i];
    }
}

// ---------------- encoder ----------------
__global__ void encoder_k(const float* __restrict__ x, const float* __restrict__ W,
                          const float* __restrict__ b, float* __restrict__ h) {
    int idx = blockIdx.x * blockDim.x + threadIdx.x;
    if (idx >= NHIT * HD) return;
    int n = idx >> 7, j = idx & 127;
    float acc = b[j];
    #pragma unroll
    for (int k = 0; k < 4; k++) acc = fmaf(x[n * 4 + k], W[k * HD + j], acc);
    h[idx] = fmaxf(acc, 0.f);
}

// ---------------- planar edge aggregation (warp per node, CSR) ----------------
__global__ void planar_agg(const float* __restrict__ b1, int p) {
    int warp = (blockIdx.x * blockDim.x + threadIdx.x) >> 5;
    if (warp >= NHIT) return;
    int lane = threadIdx.x & 31;
    int n = warp;
    float4 a = *reinterpret_cast<const float4*>(&g_A[n * HD + lane * 4]);
    float4 bb = *reinterpret_cast<const float4*>(&b1[lane * 4]);
    int s = g_offE[p][n], e = g_offE[p][n + 1];
    float4 acc = make_float4(0.f, 0.f, 0.f, 0.f);
    for (int i = s; i < e; i++) {
        int src = g_csrE[p][i];
        float4 b = *reinterpret_cast<const float4*>(&g_B[src * HD + lane * 4]);
        acc.x += fmaxf(a.x + b.x + bb.x, 0.f);
        acc.y += fmaxf(a.y + b.y + bb.y, 0.f);
        acc.z += fmaxf(a.z + b.z + bb.z, 0.f);
        acc.w += fmaxf(a.w + b.w + bb.w, 0.f);
    }
    float inv = (e > s) ? 1.f / (float)(e - s) : 0.f;
    *reinterpret_cast<float4*>(&g_mr[n * HD + lane * 4]) =
        make_float4(acc.x * inv, acc.y * inv, acc.z * inv, acc.w * inv);
}

// ---------------- nexus forward ----------------
__global__ void nexus_fwd(const float* __restrict__ h0, const float* __restrict__ h1,
                          const float* __restrict__ h2) {
    int warp = (blockIdx.x * blockDim.x + threadIdx.x) >> 5;
    if (warp >= NSP) return;
    int lane = threadIdx.x & 31;
    int s = warp;
    const float* hs[3] = {h0, h1, h2};
    float4 tot = make_float4(0.f, 0.f, 0.f, 0.f);
    #pragma unroll
    for (int p = 0; p < 3; p++) {
        int st = g_offF[p][s], en = g_offF[p][s + 1];
        float4 acc = make_float4(0.f, 0.f, 0.f, 0.f);
        for (int i = st; i < en; i++) {
            int hit = g_csrF[p][i];
            float4 v = *reinterpret_cast<const float4*>(&hs[p][hit * HD + lane * 4]);
            acc.x += v.x; acc.y += v.y; acc.z += v.z; acc.w += v.w;
        }
        if (en > st) {
            float inv = 1.f / (float)(en - st);
            tot.x += acc.x * inv; tot.y += acc.y * inv;
            tot.z += acc.z * inv; tot.w += acc.w * inv;
        }
    }
    *reinterpret_cast<float4*>(&g_spsum[s * HD + lane * 4]) = tot;
}

// ---------------- nexus backward ----------------
__global__ void nexus_back(int p) {
    int warp = (blockIdx.x * blockDim.x + threadIdx.x) >> 5;
    if (warp >= NHIT) return;
    int lane = threadIdx.x & 31;
    int n = warp;
    int st = g_offB[p][n], en = g_offB[p][n + 1];
    float4 acc = make_float4(0.f, 0.f, 0.f, 0.f);
    for (int i = st; i < en; i++) {
        int spi = g_csrB[p][i];
        float4 v = *reinterpret_cast<const float4*>(&g_sp[spi * HD + lane * 4]);
        acc.x += v.x; acc.y += v.y; acc.z += v.z; acc.w += v.w;
    }
    float inv = (en > st) ? 1.f / (float)(en - st) : 0.f;
    *reinterpret_cast<float4*>(&g_back[n * HD + lane * 4]) =
        make_float4(acc.x * inv, acc.y * inv, acc.z * inv, acc.w * inv);
}

// ---------------- decoder ----------------
__global__ void decoder_k(const float* __restrict__ h, const float* __restrict__ Wsem,
                          const float* __restrict__ bsem, float* __restrict__ out) {
    int warp = (blockIdx.x * blockDim.x + threadIdx.x) >> 5;
    if (warp >= NHIT) return;
    int lane = threadIdx.x & 31;
    int n = warp;
    float hv[4];
    #pragma unroll
    for (int t = 0; t < 4; t++) hv[t] = h[n * HD + lane + t * 32];
    #pragma unroll
    for (int c = 0; c < NCLASS; c++) {
        float s = 0.f;
        #pragma unroll
        for (int t = 0; t < 4; t++) s = fmaf(hv[t], Wsem[(lane + t * 32) * NCLASS + c], s);
        #pragma unroll
        for (int d = 16; d > 0; d >>= 1) s += __shfl_down_sync(0xffffffffu, s, d);
        if (lane == 0) out[n * NCLASS + c] = s + bsem[c];
    }
}

// ---------------- host ----------------
extern "C" void kernel_launch(void* const* d_in, const int* in_sizes, int n_in,
                              void* d_out, int out_size) {
    int xi[3], ei[3], ni[3];
    if (in_sizes[1] == 2 * NEDGE) {
        for (int p = 0; p < 3; p++) { xi[p] = 3 * p; ei[p] = 3 * p + 1; ni[p] = 3 * p + 2; }
    } else {
        for (int p = 0; p < 3; p++) { xi[p] = p; ei[p] = 3 + p; ni[p] = 6 + p; }
    }
    const float* x[3]; const int* edge[3]; const int* nexus[3];
    for (int p = 0; p < 3; p++) {
        x[p] = (const float*)d_in[xi[p]];
        edge[p] = (const int*)d_in[ei[p]];
        nexus[p] = (const int*)d_in[ni[p]];
    }
    const float* W_enc  = (const float*)d_in[9];
    const float* b_enc  = (const float*)d_in[10];
    const float* W_msg1 = (const float*)d_in[11];
    const float* b_msg1 = (const float*)d_in[12];
    const float* W_msg2 = (const float*)d_in[13];
    const float* b_msg2 = (const float*)d_in[14];
    const float* W_upd  = (const float*)d_in[15];
    const float* b_upd  = (const float*)d_in[16];
    const float* W_sp   = (const float*)d_in[17];
    const float* b_sp   = (const float*)d_in[18];
    const float* W_nx   = (const float*)d_in[19];
    const float* b_nx   = (const float*)d_in[20];
    const float* W_sem  = (const float*)d_in[21];
    const float* b_sem  = (const float*)d_in[22];

    float *ph, *pA, *pB, *pmr, *pagg, *pspsum, *psp, *pback;
    int* pdeg;
    cudaGetSymbolAddress((void**)&ph, g_h);
    cudaGetSymbolAddress((void**)&pA, g_A);
    cudaGetSymbolAddress((void**)&pB, g_B);
    cudaGetSymbolAddress((void**)&pmr, g_mr);
    cudaGetSymbolAddress((void**)&pagg, g_agg);
    cudaGetSymbolAddress((void**)&pspsum, g_spsum);
    cudaGetSymbolAddress((void**)&psp, g_sp);
    cudaGetSymbolAddress((void**)&pback, g_back);
    cudaGetSymbolAddress((void**)&pdeg, g_deg);

    cudaFuncSetAttribute(gemm_mma, cudaFuncAttributeMaxDynamicSharedMemorySize, SM_TOTAL);

    auto HB = [&](int b, int p) { return ph + ((size_t)(b * 3 + p)) * NHIT * HD; };

    const int T = 256;
    dim3 gG((NHIT + 127) / 128);
    int gWarp = (NHIT * 32 + T - 1) / T;

    // --- CSR build ---
    zero_counts<<<(NHIT + T - 1) / T, T>>>();
    dim3 gCnt((NEDGE + T - 1) / T, 3);
    count_all<<<gCnt, T>>>(edge[0], edge[1], edge[2], nexus[0], nexus[1], nexus[2]);
    scan_excl_all<<<9, 1024>>>();
    fill_all<<<gCnt, T>>>(edge[0], edge[1], edge[2], nexus[0], nexus[1], nexus[2]);

    // --- weight prep (chunks: 0=W1top 1=W1bot 2=Wmsg2 3,4=Wupd 5=Wsp 6,7=Wnx) ---
    prep_w<<<256, 256>>>(W_msg1, W_msg1 + 128 * 128, W_msg2,
                         W_upd, W_upd + 128 * 128, W_sp,
                         W_nx, W_nx + 128 * 128);

    // --- encoder ---
    for (int p = 0; p < 3; p++)
        encoder_k<<<(NHIT * HD + T - 1) / T, T>>>(x[p], W_enc, b_enc, HB(0, p));

    const int cur = 0;
    for (int it = 0; it < 3; it++) {
        for (int p = 0; p < 3; p++) {
            gemm_mma<<<gG, T, SM_TOTAL>>>(HB(cur, p), nullptr, 0, 1, nullptr, nullptr,
                                          nullptr, pA, NHIT, EPI_PLAIN);
            gemm_mma<<<gG, T, SM_TOTAL>>>(HB(cur, p), nullptr, 1, 1, nullptr, nullptr,
                                          nullptr, pB, NHIT, EPI_PLAIN);
            planar_agg<<<gWarp, T>>>(b_msg1, p);
            gemm_mma<<<gG, T, SM_TOTAL>>>(pmr, nullptr, 2, 1, b_msg2, nullptr,
                                          pdeg + p * NHIT, pagg, NHIT, EPI_MASKBIAS);
            gemm_mma<<<gG, T, SM_TOTAL>>>(HB(cur, p), pagg, 3, 2, b_upd, HB(cur, p),
                                          nullptr, HB(1 - cur, p), NHIT, EPI_RESRELU);
        }
        nexus_fwd<<<gWarp, T>>>(HB(1 - cur, 0), HB(1 - cur, 1), HB(1 - cur, 2));
        gemm_mma<<<gG, T, SM_TOTAL>>>(pspsum, nullptr, 5, 1, b_sp, nullptr,
                                      nullptr, psp, NSP, EPI_RELU);
        for (int p = 0; p < 3; p++) {
            nexus_back<<<gWarp, T>>>(p);
            gemm_mma<<<gG, T, SM_TOTAL>>>(HB(1 - cur, p), pback, 6, 2, b_nx, HB(1 - cur, p),
                                          nullptr, HB(cur, p), NHIT, EPI_RESRELU);
        }
    }

    for (int p = 0; p < 3; p++)
        decoder_k<<<gWarp, T>>>(HB(0, p), W_sem, b_sem,
                                ((float*)d_out) + (size_t)p * NHIT * NCLASS);
}

// round 5
// speedup vs baseline: 2.5839x; 1.1865x over previous
#include <cuda_runtime.h>
#include <cuda_bf16.h>
#include <cstdint>

#define NHIT 30000
#define NEDGE 90000
#define NSP 30000
#define HD 128
#define NCLASS 5
#define PSTRIDE (NHIT * HD)

// ---------------- device scratch ----------------
__device__ float g_h[2][3][NHIT * HD];
__device__ float g_A[3][NHIT * HD];
__device__ float g_B[3][NHIT * HD];
__device__ float g_mr[3][NHIT * HD];
__device__ float g_agg[3][NHIT * HD];
__device__ float g_spsum[NSP * HD];
__device__ float g_sp[NSP * HD];
__device__ float g_back[3][NHIT * HD];

// prepped weights: 8 chunks x {hi,lo} x 2 k-stages x (128n x 64k bf16, swizzled)
__device__ uint4 g_wbuf[8][2][2][1024];

__device__ int g_deg[3][NHIT];
__device__ int g_cf[3][NSP];
__device__ int g_cb[3][NHIT];
__device__ int g_offE[3][NHIT + 1];
__device__ int g_offF[3][NSP + 1];
__device__ int g_offB[3][NHIT + 1];
__device__ int g_csrE[3][NEDGE];
__device__ int g_csrF[3][NSP];
__device__ int g_csrB[3][NSP];
__device__ int g_curE[3][NHIT];
__device__ int g_curF[3][NSP];
__device__ int g_curB[3][NHIT];

enum { EPI_PLAIN = 0, EPI_RELU = 1, EPI_RESRELU = 2, EPI_MASKBIAS = 3 };

// ---------------- helpers ----------------
__device__ __forceinline__ uint32_t s2u(const void* p) {
    return (uint32_t)__cvta_generic_to_shared(p);
}
__device__ __forceinline__ uint32_t pack2(float a, float b) {
    __nv_bfloat162 t = __floats2bfloat162_rn(a, b);
    return *reinterpret_cast<uint32_t*>(&t);
}
__device__ __forceinline__ float lopart(float v) {
    __nv_bfloat16 h = __float2bfloat16(v);
    return v - __bfloat162float(h);
}
// swizzled byte offset within a [128 rows x 64 k] bf16 tile (128B rows)
__device__ __forceinline__ uint32_t swz(int row, int k) {
    return (uint32_t)(row * 128 + ((((k >> 3) ^ row) & 7) << 4) + (k & 7) * 2);
}
__device__ __forceinline__ void ldsm4(uint32_t* r, uint32_t addr) {
    asm volatile("ldmatrix.sync.aligned.m8n8.x4.shared.b16 {%0,%1,%2,%3}, [%4];"
                 : "=r"(r[0]), "=r"(r[1]), "=r"(r[2]), "=r"(r[3]) : "r"(addr));
}
__device__ __forceinline__ void mma16816(float* c, const uint32_t* a, uint32_t b0, uint32_t b1) {
    asm volatile(
        "mma.sync.aligned.m16n8k16.row.col.f32.bf16.bf16.f32 "
        "{%0,%1,%2,%3}, {%4,%5,%6,%7}, {%8,%9}, {%0,%1,%2,%3};"
        : "+f"(c[0]), "+f"(c[1]), "+f"(c[2]), "+f"(c[3])
        : "r"(a[0]), "r"(a[1]), "r"(a[2]), "r"(a[3]), "r"(b0), "r"(b1));
}

// gemm_mma smem layout (64KB)
#define SM_AHI 0
#define SM_ALO 16384
#define SM_BHI 32768
#define SM_BLO 49152
#define SM_TOTAL 65536
// gemm_dual smem layout (96KB): A holds both 64-k stages
#define DU_AHI 0
#define DU_ALO 32768
#define DU_BHI 65536
#define DU_BLO 81920
#define DU_TOTAL 98304

// ---------------- weight prep: transpose + hi/lo bf16 + swizzle ----------------
__global__ void prep_w(const float* w0, const float* w1, const float* w2,
                       const float* w3, const float* w4, const float* w5,
                       const float* w6, const float* w7) {
    int id = blockIdx.x * blockDim.x + threadIdx.x;   // 65536 total
    int c = id >> 13;
    int rem = id & 8191;
    int s = rem >> 12;
    int rem2 = rem & 4095;
    int n = rem2 >> 5;
    int kp = (rem2 & 31) * 2;
    const float* Wc = (c == 0) ? w0 : (c == 1) ? w1 : (c == 2) ? w2 : (c == 3) ? w3
                    : (c == 4) ? w4 : (c == 5) ? w5 : (c == 6) ? w6 : w7;
    float v0 = Wc[(s * 64 + kp) * 128 + n];
    float v1 = Wc[(s * 64 + kp + 1) * 128 + n];
    uint32_t o = swz(n, kp);
    *reinterpret_cast<uint32_t*>((char*)&g_wbuf[c][0][s][0] + o) = pack2(v0, v1);
    *reinterpret_cast<uint32_t*>((char*)&g_wbuf[c][1][s][0] + o) = pack2(lopart(v0), lopart(v1));
}

// ---------------- shared mainloop fragment ----------------
#define MAINLOOP(ABASE) \
    _Pragma("unroll") \
    for (int k16 = 0; k16 < 4; k16++) { \
        uint32_t ahi[2][4], alo[2][4]; \
        _Pragma("unroll") \
        for (int mt = 0; mt < 2; mt++) { \
            int row = mwarp * 32 + mt * 16 + a_row_in16; \
            uint32_t o = (uint32_t)(row * 128 + ((((k16 * 2 + a_kb) ^ row) & 7) << 4)); \
            ldsm4(ahi[mt], sb + (ABASE) + o); \
            ldsm4(alo[mt], sb + (ABASE) + 16384 * 2 / 2 * 0 + (ALO_OFF) + o); \
        } \
        _Pragma("unroll") \
        for (int ntp = 0; ntp < 4; ntp++) { \
            int nrow = nwarp * 64 + ntp * 16 + b_row_in16; \
            uint32_t o = (uint32_t)(nrow * 128 + ((((k16 * 2 + b_kb) ^ nrow) & 7) << 4)); \
            uint32_t bhi[4], blo[4]; \
            ldsm4(bhi, sb + (BHI_OFF) + o); \
            ldsm4(blo, sb + (BLO_OFF) + o); \
            _Pragma("unroll") \
            for (int half = 0; half < 2; half++) { \
                int nt = ntp * 2 + half; \
                _Pragma("unroll") \
                for (int mt = 0; mt < 2; mt++) { \
                    mma16816(C[mt][nt], ahi[mt], bhi[half * 2], bhi[half * 2 + 1]); \
                    mma16816(C[mt][nt], ahi[mt], blo[half * 2], blo[half * 2 + 1]); \
                    mma16816(C[mt][nt], alo[mt], bhi[half * 2], bhi[half * 2 + 1]); \
                } \
            } \
        } \
    }

// ---------------- HMMA split-bf16 SGEMM (plane-batched): out[M,128] = [A0|A1]@W ----------------
__global__ __launch_bounds__(256, 2) void gemm_mma(
    const float* __restrict__ A0, const float* __restrict__ A1,
    int sA, int wc0, int nchunks,
    const float* __restrict__ bias, const float* __restrict__ resid,
    const int* __restrict__ mask, int sMask,
    float* __restrict__ out, int M, int epi)
{
    extern __shared__ char smem[];
    uint32_t sb = s2u(smem);
    int tid = threadIdx.x;
    int wid = tid >> 5, lane = tid & 31;
    int mwarp = wid & 3, nwarp = wid >> 2;
    int row0 = blockIdx.x * 128;
    int pl = blockIdx.y;
    const float* A0p = A0 + (size_t)pl * sA;
    const float* A1p = A1 ? (A1 + (size_t)pl * sA) : nullptr;
    const float* residp = resid ? (resid + (size_t)pl * sA) : nullptr;
    const int* maskp = mask ? (mask + (size_t)pl * sMask) : nullptr;
    float* outp = out + (size_t)pl * sA;

    float C[2][8][4];
    #pragma unroll
    for (int mt = 0; mt < 2; mt++)
        #pragma unroll
        for (int nt = 0; nt < 8; nt++)
            #pragma unroll
            for (int q = 0; q < 4; q++) C[mt][nt][q] = 0.f;

    int a_row_in16 = (lane & 7) + ((lane >> 3) & 1) * 8;
    int a_kb = (lane >> 4) & 1;
    int b_row_in16 = (lane & 7) + ((lane >> 4) & 1) * 8;
    int b_kb = (lane >> 3) & 1;

    for (int ch = 0; ch < nchunks; ch++) {
        const float* Ap = ch ? A1p : A0p;
        for (int s = 0; s < 2; s++) {
            #pragma unroll
            for (int l = 0; l < 8; l++) {
                int i = l * 256 + tid;
                int r = i >> 4, c4 = (i & 15) * 4;
                float4 v = make_float4(0.f, 0.f, 0.f, 0.f);
                int row = row0 + r;
                if (row < M)
                    v = *reinterpret_cast<const float4*>(&Ap[(size_t)row * 128 + s * 64 + c4]);
                uint32_t o = swz(r, c4);
                *reinterpret_cast<uint2*>(smem + SM_AHI + o) =
                    make_uint2(pack2(v.x, v.y), pack2(v.z, v.w));
                *reinterpret_cast<uint2*>(smem + SM_ALO + o) =
                    make_uint2(pack2(lopart(v.x), lopart(v.y)), pack2(lopart(v.z), lopart(v.w)));
            }
            const uint4* bh = &g_wbuf[wc0 + ch][0][s][0];
            const uint4* bl = &g_wbuf[wc0 + ch][1][s][0];
            #pragma unroll
            for (int l = 0; l < 4; l++) {
                int i = l * 256 + tid;
                *reinterpret_cast<uint4*>(smem + SM_BHI + i * 16) = bh[i];
                *reinterpret_cast<uint4*>(smem + SM_BLO + i * 16) = bl[i];
            }
            __syncthreads();

            #pragma unroll
            for (int k16 = 0; k16 < 4; k16++) {
                uint32_t ahi[2][4], alo[2][4];
                #pragma unroll
                for (int mt = 0; mt < 2; mt++) {
                    int row = mwarp * 32 + mt * 16 + a_row_in16;
                    uint32_t o = (uint32_t)(row * 128 + ((((k16 * 2 + a_kb) ^ row) & 7) << 4));
                    ldsm4(ahi[mt], sb + SM_AHI + o);
                    ldsm4(alo[mt], sb + SM_ALO + o);
                }
                #pragma unroll
                for (int ntp = 0; ntp < 4; ntp++) {
                    int nrow = nwarp * 64 + ntp * 16 + b_row_in16;
                    uint32_t o = (uint32_t)(nrow * 128 + ((((k16 * 2 + b_kb) ^ nrow) & 7) << 4));
                    uint32_t bhi[4], blo[4];
                    ldsm4(bhi, sb + SM_BHI + o);
                    ldsm4(blo, sb + SM_BLO + o);
                    #pragma unroll
                    for (int half = 0; half < 2; half++) {
                        int nt = ntp * 2 + half;
                        #pragma unroll
                        for (int mt = 0; mt < 2; mt++) {
                            mma16816(C[mt][nt], ahi[mt], bhi[half * 2], bhi[half * 2 + 1]);
                            mma16816(C[mt][nt], ahi[mt], blo[half * 2], blo[half * 2 + 1]);
                            mma16816(C[mt][nt], alo[mt], bhi[half * 2], bhi[half * 2 + 1]);
                        }
                    }
                }
            }
            __syncthreads();
        }
    }

    int qrow = lane >> 2;
    int qcol = (lane & 3) * 2;
    #pragma unroll
    for (int mt = 0; mt < 2; mt++) {
        #pragma unroll
        for (int half = 0; half < 2; half++) {
            int row = row0 + mwarp * 32 + mt * 16 + qrow + half * 8;
            if (row >= M) continue;
            bool mk = (epi == EPI_MASKBIAS) ? (maskp[row] > 0) : false;
            #pragma unroll
            for (int nt = 0; nt < 8; nt++) {
                int col = nwarp * 64 + nt * 8 + qcol;
                float v0 = C[mt][nt][half * 2 + 0];
                float v1 = C[mt][nt][half * 2 + 1];
                float o0, o1;
                if (epi == EPI_PLAIN) { o0 = v0; o1 = v1; }
                else if (epi == EPI_RELU) {
                    o0 = fmaxf(v0 + bias[col], 0.f);
                    o1 = fmaxf(v1 + bias[col + 1], 0.f);
                } else if (epi == EPI_RESRELU) {
                    float2 rr = *reinterpret_cast<const float2*>(&residp[(size_t)row * 128 + col]);
                    o0 = rr.x + fmaxf(v0 + bias[col], 0.f);
                    o1 = rr.y + fmaxf(v1 + bias[col + 1], 0.f);
                } else {
                    o0 = mk ? (v0 + bias[col]) : 0.f;
                    o1 = mk ? (v1 + bias[col + 1]) : 0.f;
                }
                *reinterpret_cast<float2*>(&outp[(size_t)row * 128 + col]) = make_float2(o0, o1);
            }
        }
    }
}

// ---------------- dual-output GEMM: stages A once, two weight sets ----------------
__global__ __launch_bounds__(256, 2) void gemm_dual(
    const float* __restrict__ A, int sA, int wc0, int wc1,
    float* __restrict__ out0, float* __restrict__ out1, int M)
{
    extern __shared__ char smem[];
    uint32_t sb = s2u(smem);
    int tid = threadIdx.x;
    int wid = tid >> 5, lane = tid & 31;
    int mwarp = wid & 3, nwarp = wid >> 2;
    int row0 = blockIdx.x * 128;
    int pl = blockIdx.y;
    const float* Ap = A + (size_t)pl * sA;
    float* o0 = out0 + (size_t)pl * sA;
    float* o1 = out1 + (size_t)pl * sA;

    int a_row_in16 = (lane & 7) + ((lane >> 3) & 1) * 8;
    int a_kb = (lane >> 4) & 1;
    int b_row_in16 = (lane & 7) + ((lane >> 4) & 1) * 8;
    int b_kb = (lane >> 3) & 1;

    // stage A (both 64-k halves) once
    #pragma unroll
    for (int l = 0; l < 16; l++) {
        int i = l * 256 + tid;
        int r = i >> 5, c4 = (i & 31) * 4;
        int s = c4 >> 6, k = c4 & 63;
        float4 v = make_float4(0.f, 0.f, 0.f, 0.f);
        int row = row0 + r;
        if (row < M)
            v = *reinterpret_cast<const float4*>(&Ap[(size_t)row * 128 + c4]);
        uint32_t o = s * 16384 + swz(r, k);
        *reinterpret_cast<uint2*>(smem + DU_AHI + o) =
            make_uint2(pack2(v.x, v.y), pack2(v.z, v.w));
        *reinterpret_cast<uint2*>(smem + DU_ALO + o) =
            make_uint2(pack2(lopart(v.x), lopart(v.y)), pack2(lopart(v.z), lopart(v.w)));
    }

    int qrow = lane >> 2;
    int qcol = (lane & 3) * 2;

    #pragma unroll
    for (int w = 0; w < 2; w++) {
        int wc = w ? wc1 : wc0;
        float* op = w ? o1 : o0;
        float C[2][8][4];
        #pragma unroll
        for (int mt = 0; mt < 2; mt++)
            #pragma unroll
            for (int nt = 0; nt < 8; nt++)
                #pragma unroll
                for (int q = 0; q < 4; q++) C[mt][nt][q] = 0.f;

        for (int s = 0; s < 2; s++) {
            __syncthreads();    // protect B buffer (and initial A staging)
            const uint4* bh = &g_wbuf[wc][0][s][0];
            const uint4* bl = &g_wbuf[wc][1][s][0];
            #pragma unroll
            for (int l = 0; l < 4; l++) {
                int i = l * 256 + tid;
                *reinterpret_cast<uint4*>(smem + DU_BHI + i * 16) = bh[i];
                *reinterpret_cast<uint4*>(smem + DU_BLO + i * 16) = bl[i];
            }
            __syncthreads();

            uint32_t abase = (uint32_t)(s * 16384);
            #pragma unroll
            for (int k16 = 0; k16 < 4; k16++) {
                uint32_t ahi[2][4], alo[2][4];
                #pragma unroll
                for (int mt = 0; mt < 2; mt++) {
                    int row = mwarp * 32 + mt * 16 + a_row_in16;
                    uint32_t o = (uint32_t)(row * 128 + ((((k16 * 2 + a_kb) ^ row) & 7) << 4));
                    ldsm4(ahi[mt], sb + DU_AHI + abase + o);
                    ldsm4(alo[mt], sb + DU_ALO + abase + o);
                }
                #pragma unroll
                for (int ntp = 0; ntp < 4; ntp++) {
                    int nrow = nwarp * 64 + ntp * 16 + b_row_in16;
                    uint32_t o = (uint32_t)(nrow * 128 + ((((k16 * 2 + b_kb) ^ nrow) & 7) << 4));
                    uint32_t bhi[4], blo[4];
                    ldsm4(bhi, sb + DU_BHI + o);
                    ldsm4(blo, sb + DU_BLO + o);
                    #pragma unroll
                    for (int half = 0; half < 2; half++) {
                        int nt = ntp * 2 + half;
                        #pragma unroll
                        for (int mt = 0; mt < 2; mt++) {
                            mma16816(C[mt][nt], ahi[mt], bhi[half * 2], bhi[half * 2 + 1]);
                            mma16816(C[mt][nt], ahi[mt], blo[half * 2], blo[half * 2 + 1]);
                            mma16816(C[mt][nt], alo[mt], bhi[half * 2], bhi[half * 2 + 1]);
                        }
                    }
                }
            }
        }

        #pragma unroll
        for (int mt = 0; mt < 2; mt++) {
            #pragma unroll
            for (int half = 0; half < 2; half++) {
                int row = row0 + mwarp * 32 + mt * 16 + qrow + half * 8;
                if (row >= M) continue;
                #pragma unroll
                for (int nt = 0; nt < 8; nt++) {
                    int col = nwarp * 64 + nt * 8 + qcol;
                    *reinterpret_cast<float2*>(&op[(size_t)row * 128 + col]) =
                        make_float2(C[mt][nt][half * 2], C[mt][nt][half * 2 + 1]);
                }
            }
        }
    }
}

// ---------------- CSR build ----------------
__global__ void zero_counts() {
    int i = blockIdx.x * blockDim.x + threadIdx.x;
    if (i < NHIT) {
        #pragma unroll
        for (int p = 0; p < 3; p++) { g_deg[p][i] = 0; g_cb[p][i] = 0; }
    }
    if (i < NSP) {
        #pragma unroll
        for (int p = 0; p < 3; p++) g_cf[p][i] = 0;
    }
}

__global__ void count_all(const int* __restrict__ e0, const int* __restrict__ e1,
                          const int* __restrict__ e2, const int* __restrict__ n0,
                          const int* __restrict__ n1, const int* __restrict__ n2) {
    int p = blockIdx.y;
    const int* e = (p == 0) ? e0 : (p == 1) ? e1 : e2;
    const int* nx = (p == 0) ? n0 : (p == 1) ? n1 : n2;
    int i = blockIdx.x * blockDim.x + threadIdx.x;
    if (i < NEDGE) atomicAdd(&g_deg[p][e[NEDGE + i]], 1);
    if (i < NSP) {
        atomicAdd(&g_cf[p][nx[NSP + i]], 1);
        atomicAdd(&g_cb[p][nx[i]], 1);
    }
}

__global__ void scan_excl_all() {
    int sel = blockIdx.x / 3, p = blockIdx.x % 3;
    const int* in; int* out; int* cur; int n;
    if (sel == 0)      { in = g_deg[p]; out = g_offE[p]; cur = g_curE[p]; n = NHIT; }
    else if (sel == 1) { in = g_cf[p];  out = g_offF[p]; cur = g_curF[p]; n = NSP; }
    else               { in = g_cb[p];  out = g_offB[p]; cur = g_curB[p]; n = NHIT; }
    __shared__ int wsum[32];
    __shared__ int carry;
    int tid = threadIdx.x;
    if (tid == 0) carry = 0;
    __syncthreads();
    for (int base = 0; base < n; base += 1024) {
        int i = base + tid;
        int v = (i < n) ? in[i] : 0;
        int x = v;
        #pragma unroll
        for (int d = 1; d < 32; d <<= 1) {
            int y = __shfl_up_sync(0xffffffffu, x, d);
            if ((tid & 31) >= d) x += y;
        }
        if ((tid & 31) == 31) wsum[tid >> 5] = x;
        __syncthreads();
        if (tid < 32) {
            int s = wsum[tid];
            #pragma unroll
            for (int d = 1; d < 32; d <<= 1) {
                int y = __shfl_up_sync(0xffffffffu, s, d);
                if (tid >= d) s += y;
            }
            wsum[tid] = s;
        }
        __syncthreads();
        int woff = (tid >= 32) ? wsum[(tid >> 5) - 1] : 0;
        int incl = carry + woff + x;
        if (i < n) { out[i] = incl - v; cur[i] = incl - v; }
        __syncthreads();
        if (tid == 1023) carry = incl;
        __syncthreads();
    }
    if (tid == 0) out[n] = carry;
}

__global__ void fill_all(const int* __restrict__ e0, const int* __restrict__ e1,
                         const int* __restrict__ e2, const int* __restrict__ n0,
                         const int* __restrict__ n1, const int* __restrict__ n2) {
    int p = blockIdx.y;
    const int* e = (p == 0) ? e0 : (p == 1) ? e1 : e2;
    const int* nx = (p == 0) ? n0 : (p == 1) ? n1 : n2;
    int i = blockIdx.x * blockDim.x + threadIdx.x;
    if (i < NEDGE) {
        int dst = e[NEDGE + i];
        g_csrE[p][atomicAdd(&g_curE[p][dst], 1)] = e[i];
    }
    if (i < NSP) {
        int s = nx[NSP + i];
        g_csrF[p][atomicAdd(&g_curF[p][s], 1)] = nx[i];
        int h = nx[i];
        g_csrB[p][atomicAdd(&g_curB[p][h], 1)] = nx[NSP + i];
    }
}

// ---------------- encoder (plane-batched) ----------------
__global__ void encoder_k(const float* __restrict__ x0, const float* __restrict__ x1,
                          const float* __restrict__ x2, const float* __restrict__ W,
                          const float* __restrict__ b, float* __restrict__ hbase) {
    int p = blockIdx.y;
    const float* x = (p == 0) ? x0 : (p == 1) ? x1 : x2;
    float* h = hbase + (size_t)p * PSTRIDE;
    int idx = blockIdx.x * blockDim.x + threadIdx.x;
    if (idx >= NHIT * HD) return;
    int n = idx >> 7, j = idx & 127;
    float acc = b[j];
    #pragma unroll
    for (int k = 0; k < 4; k++) acc = fmaf(x[n * 4 + k], W[k * HD + j], acc);
    h[idx] = fmaxf(acc, 0.f);
}

// ---------------- planar edge aggregation (warp per node, plane-batched) ----------------
__global__ void planar_agg(const float* __restrict__ b1) {
    int p = blockIdx.y;
    int warp = (blockIdx.x * blockDim.x + threadIdx.x) >> 5;
    if (warp >= NHIT) return;
    int lane = threadIdx.x & 31;
    int n = warp;
    float4 a = *reinterpret_cast<const float4*>(&g_A[p][n * HD + lane * 4]);
    float4 bb = *reinterpret_cast<const float4*>(&b1[lane * 4]);
    int s = g_offE[p][n], e = g_offE[p][n + 1];
    float4 acc = make_float4(0.f, 0.f, 0.f, 0.f);
    for (int i = s; i < e; i++) {
        int src = g_csrE[p][i];
        float4 b = *reinterpret_cast<const float4*>(&g_B[p][src * HD + lane * 4]);
        acc.x += fmaxf(a.x + b.x + bb.x, 0.f);
        acc.y += fmaxf(a.y + b.y + bb.y, 0.f);
        acc.z += fmaxf(a.z + b.z + bb.z, 0.f);
        acc.w += fmaxf(a.w + b.w + bb.w, 0.f);
    }
    float inv = (e > s) ? 1.f / (float)(e - s) : 0.f;
    *reinterpret_cast<float4*>(&g_mr[p][n * HD + lane * 4]) =
        make_float4(acc.x * inv, acc.y * inv, acc.z * inv, acc.w * inv);
}

// ---------------- nexus forward ----------------
__global__ void nexus_fwd(const float* __restrict__ hbase) {
    int warp = (blockIdx.x * blockDim.x + threadIdx.x) >> 5;
    if (warp >= NSP) return;
    int lane = threadIdx.x & 31;
    int s = warp;
    float4 tot = make_float4(0.f, 0.f, 0.f, 0.f);
    #pragma unroll
    for (int p = 0; p < 3; p++) {
        const float* h = hbase + (size_t)p * PSTRIDE;
        int st = g_offF[p][s], en = g_offF[p][s + 1];
        float4 acc = make_float4(0.f, 0.f, 0.f, 0.f);
        for (int i = st; i < en; i++) {
            int hit = g_csrF[p][i];
            float4 v = *reinterpret_cast<const float4*>(&h[hit * HD + lane * 4]);
            acc.x += v.x; acc.y += v.y; acc.z += v.z; acc.w += v.w;
        }
        if (en > st) {
            float inv = 1.f / (float)(en - st);
            tot.x += acc.x * inv; tot.y += acc.y * inv;
            tot.z += acc.z * inv; tot.w += acc.w * inv;
        }
    }
    *reinterpret_cast<float4*>(&g_spsum[s * HD + lane * 4]) = tot;
}

// ---------------- nexus backward (plane-batched) ----------------
__global__ void nexus_back() {
    int p = blockIdx.y;
    int warp = (blockIdx.x * blockDim.x + threadIdx.x) >> 5;
    if (warp >= NHIT) return;
    int lane = threadIdx.x & 31;
    int n = warp;
    int st = g_offB[p][n], en = g_offB[p][n + 1];
    float4 acc = make_float4(0.f, 0.f, 0.f, 0.f);
    for (int i = st; i < en; i++) {
        int spi = g_csrB[p][i];
        float4 v = *reinterpret_cast<const float4*>(&g_sp[spi * HD + lane * 4]);
        acc.x += v.x; acc.y += v.y; acc.z += v.z; acc.w += v.w;
    }
    float inv = (en > st) ? 1.f / (float)(en - st) : 0.f;
    *reinterpret_cast<float4*>(&g_back[p][n * HD + lane * 4]) =
        make_float4(acc.x * inv, acc.y * inv, acc.z * inv, acc.w * inv);
}

// ---------------- decoder (plane-batched) ----------------
__global__ void decoder_k(const float* __restrict__ hbase, const float* __restrict__ Wsem,
                          const float* __restrict__ bsem, float* __restrict__ out) {
    int p = blockIdx.y;
    const float* h = hbase + (size_t)p * PSTRIDE;
    float* o = out + (size_t)p * NHIT * NCLASS;
    int warp = (blockIdx.x * blockDim.x + threadIdx.x) >> 5;
    if (warp >= NHIT) return;
    int lane = threadIdx.x & 31;
    int n = warp;
    float hv[4];
    #pragma unroll
    for (int t = 0; t < 4; t++) hv[t] = h[n * HD + lane + t * 32];
    #pragma unroll
    for (int c = 0; c < NCLASS; c++) {
        float s = 0.f;
        #pragma unroll
        for (int t = 0; t < 4; t++) s = fmaf(hv[t], Wsem[(lane + t * 32) * NCLASS + c], s);
        #pragma unroll
        for (int d = 16; d > 0; d >>= 1) s += __shfl_down_sync(0xffffffffu, s, d);
        if (lane == 0) o[n * NCLASS + c] = s + bsem[c];
    }
}

// ---------------- host ----------------
extern "C" void kernel_launch(void* const* d_in, const int* in_sizes, int n_in,
                              void* d_out, int out_size) {
    int xi[3], ei[3], ni[3];
    if (in_sizes[1] == 2 * NEDGE) {
        for (int p = 0; p < 3; p++) { xi[p] = 3 * p; ei[p] = 3 * p + 1; ni[p] = 3 * p + 2; }
    } else {
        for (int p = 0; p < 3; p++) { xi[p] = p; ei[p] = 3 + p; ni[p] = 6 + p; }
    }
    const float* x[3]; const int* edge[3]; const int* nexus[3];
    for (int p = 0; p < 3; p++) {
        x[p] = (const float*)d_in[xi[p]];
        edge[p] = (const int*)d_in[ei[p]];
        nexus[p] = (const int*)d_in[ni[p]];
    }
    const float* W_enc  = (const float*)d_in[9];
    const float* b_enc  = (const float*)d_in[10];
    const float* W_msg1 = (const float*)d_in[11];
    const float* b_msg1 = (const float*)d_in[12];
    const float* W_msg2 = (const float*)d_in[13];
    const float* b_msg2 = (const float*)d_in[14];
    const float* W_upd  = (const float*)d_in[15];
    const float* b_upd  = (const float*)d_in[16];
    const float* W_sp   = (const float*)d_in[17];
    const float* b_sp   = (const float*)d_in[18];
    const float* W_nx   = (const float*)d_in[19];
    const float* b_nx   = (const float*)d_in[20];
    const float* W_sem  = (const float*)d_in[21];
    const float* b_sem  = (const float*)d_in[22];

    float *ph, *pA, *pB, *pmr, *pagg, *pspsum, *psp, *pback;
    int* pdeg;
    cudaGetSymbolAddress((void**)&ph, g_h);
    cudaGetSymbolAddress((void**)&pA, g_A);
    cudaGetSymbolAddress((void**)&pB, g_B);
    cudaGetSymbolAddress((void**)&pmr, g_mr);
    cudaGetSymbolAddress((void**)&pagg, g_agg);
    cudaGetSymbolAddress((void**)&pspsum, g_spsum);
    cudaGetSymbolAddress((void**)&psp, g_sp);
    cudaGetSymbolAddress((void**)&pback, g_back);
    cudaGetSymbolAddress((void**)&pdeg, g_deg);

    cudaFuncSetAttribute(gemm_mma, cudaFuncAttributeMaxDynamicSharedMemorySize, SM_TOTAL);
    cudaFuncSetAttribute(gemm_dual, cudaFuncAttributeMaxDynamicSharedMemorySize, DU_TOTAL);

    float* h0 = ph;                       // buffer 0, plane stride PSTRIDE
    float* h1 = ph + (size_t)3 * PSTRIDE; // buffer 1

    const int T = 256;
    dim3 gG3((NHIT + 127) / 128, 3);
    dim3 gG1((NHIT + 127) / 128, 1);
    dim3 gW3((NHIT * 32 + T - 1) / T, 3);
    int gW1 = (NSP * 32 + T - 1) / T;
    dim3 gE((NHIT * HD + T - 1) / T, 3);

    // --- CSR build ---
    zero_counts<<<(NHIT + T - 1) / T, T>>>();
    dim3 gCnt((NEDGE + T - 1) / T, 3);
    count_all<<<gCnt, T>>>(edge[0], edge[1], edge[2], nexus[0], nexus[1], nexus[2]);
    scan_excl_all<<<9, 1024>>>();
    fill_all<<<gCnt, T>>>(edge[0], edge[1], edge[2], nexus[0], nexus[1], nexus[2]);

    // --- weight prep (0=W1top 1=W1bot 2=Wmsg2 3=WupdT 4=WupdB 5=Wsp 6=WnxT 7=WnxB) ---
    prep_w<<<256, 256>>>(W_msg1, W_msg1 + 128 * 128, W_msg2,
                         W_upd, W_upd + 128 * 128, W_sp,
                         W_nx, W_nx + 128 * 128);

    // --- encoder ---
    encoder_k<<<gE, T>>>(x[0], x[1], x[2], W_enc, b_enc, h0);

    for (int it = 0; it < 3; it++) {
        // planar convolution (all planes in one launch each)
        gemm_dual<<<gG3, T, DU_TOTAL>>>(h0, PSTRIDE, 0, 1, pA, pB, NHIT);
        planar_agg<<<gW3, T>>>(b_msg1);
        gemm_mma<<<gG3, T, SM_TOTAL>>>(pmr, nullptr, PSTRIDE, 2, 1, b_msg2, nullptr,
                                       pdeg, NHIT, pagg, NHIT, EPI_MASKBIAS);
        gemm_mma<<<gG3, T, SM_TOTAL>>>(h0, pagg, PSTRIDE, 3, 2, b_upd, h0,
                                       nullptr, 0, h1, NHIT, EPI_RESRELU);
        // nexus convolution
        nexus_fwd<<<gW1, T>>>(h1);
        gemm_mma<<<gG1, T, SM_TOTAL>>>(pspsum, nullptr, 0, 5, 1, b_sp, nullptr,
                                       nullptr, 0, psp, NSP, EPI_RELU);
        nexus_back<<<gW3, T>>>();
        gemm_mma<<<gG3, T, SM_TOTAL>>>(h1, pback, PSTRIDE, 6, 2, b_nx, h1,
                                       nullptr, 0, h0, NHIT, EPI_RESRELU);
    }

    decoder_k<<<gW3, T>>>(h0, W_sem, b_sem, (float*)d_out);
}

// round 6
// speedup vs baseline: 2.7639x; 1.0697x over previous
#include <cuda_runtime.h>
#include <cuda_fp16.h>
#include <cstdint>

#define NHIT 30000
#define NEDGE 90000
#define NSP 30000
#define HD 128
#define NCLASS 5
#define PSTRIDE (NHIT * HD)

// ---------------- device scratch ----------------
__device__ float g_h[2][3][NHIT * HD];          // state path: fp32
__device__ __half g_A[3][NHIT * HD];            // message path: fp16
__device__ __half g_B[3][NHIT * HD];
__device__ __half g_mr[3][NHIT * HD];
__device__ __half g_agg[3][NHIT * HD];
__device__ __half g_spsum[NSP * HD];
__device__ __half g_sp[NSP * HD];
__device__ __half g_back[3][NHIT * HD];

// prepped weights: 8 chunks x {hi,lo} x 2 k-stages x (128n x 64k fp16, swizzled)
__device__ uint4 g_wbuf[8][2][2][1024];

__device__ int g_deg[3][NHIT];
__device__ int g_cf[3][NSP];
__device__ int g_cb[3][NHIT];
__device__ int g_offE[3][NHIT + 1];
__device__ int g_offF[3][NSP + 1];
__device__ int g_offB[3][NHIT + 1];
__device__ int g_csrE[3][NEDGE];
__device__ int g_csrF[3][NSP];
__device__ int g_csrB[3][NSP];
__device__ int g_curE[3][NHIT];
__device__ int g_curF[3][NSP];
__device__ int g_curB[3][NHIT];

enum { EPI_PLAIN = 0, EPI_RELU = 1, EPI_RESRELU = 2, EPI_MASKBIAS = 3 };

// ---------------- helpers ----------------
__device__ __forceinline__ uint32_t s2u(const void* p) {
    return (uint32_t)__cvta_generic_to_shared(p);
}
__device__ __forceinline__ uint32_t pack2h(float a, float b) {
    __half2 t = __floats2half2_rn(a, b);
    return *reinterpret_cast<uint32_t*>(&t);
}
__device__ __forceinline__ float lopart(float v) {
    return v - __half2float(__float2half(v));
}
// swizzled byte offset within a [128 rows x 64 k] fp16 tile (128B rows)
__device__ __forceinline__ uint32_t swz(int row, int k) {
    return (uint32_t)(row * 128 + ((((k >> 3) ^ row) & 7) << 4) + (k & 7) * 2);
}
__device__ __forceinline__ void ldsm4(uint32_t* r, uint32_t addr) {
    asm volatile("ldmatrix.sync.aligned.m8n8.x4.shared.b16 {%0,%1,%2,%3}, [%4];"
                 : "=r"(r[0]), "=r"(r[1]), "=r"(r[2]), "=r"(r[3]) : "r"(addr));
}
__device__ __forceinline__ void mma16816(float* c, const uint32_t* a, uint32_t b0, uint32_t b1) {
    asm volatile(
        "mma.sync.aligned.m16n8k16.row.col.f32.f16.f16.f32 "
        "{%0,%1,%2,%3}, {%4,%5,%6,%7}, {%8,%9}, {%0,%1,%2,%3};"
        : "+f"(c[0]), "+f"(c[1]), "+f"(c[2]), "+f"(c[3])
        : "r"(a[0]), "r"(a[1]), "r"(a[2]), "r"(a[3]), "r"(b0), "r"(b1));
}

// gemm_mma smem layout (64KB)
#define SM_AHI 0
#define SM_ALO 16384
#define SM_BHI 32768
#define SM_BLO 49152
#define SM_TOTAL 65536
// gemm_dual smem layout (96KB): A holds both 64-k stages
#define DU_AHI 0
#define DU_ALO 32768
#define DU_BHI 65536
#define DU_BLO 81920
#define DU_TOTAL 98304

// ---------------- weight prep: transpose + fp16 hi/lo + swizzle ----------------
__global__ void prep_w(const float* w0, const float* w1, const float* w2,
                       const float* w3, const float* w4, const float* w5,
                       const float* w6, const float* w7) {
    int id = blockIdx.x * blockDim.x + threadIdx.x;   // 65536 total
    int c = id >> 13;
    int rem = id & 8191;
    int s = rem >> 12;
    int rem2 = rem & 4095;
    int n = rem2 >> 5;
    int kp = (rem2 & 31) * 2;
    const float* Wc = (c == 0) ? w0 : (c == 1) ? w1 : (c == 2) ? w2 : (c == 3) ? w3
                    : (c == 4) ? w4 : (c == 5) ? w5 : (c == 6) ? w6 : w7;
    float v0 = Wc[(s * 64 + kp) * 128 + n];
    float v1 = Wc[(s * 64 + kp + 1) * 128 + n];
    uint32_t o = swz(n, kp);
    *reinterpret_cast<uint32_t*>((char*)&g_wbuf[c][0][s][0] + o) = pack2h(v0, v1);
    *reinterpret_cast<uint32_t*>((char*)&g_wbuf[c][1][s][0] + o) = pack2h(lopart(v0), lopart(v1));
}

// ---------------- HMMA split-fp16 GEMM (plane-batched) ----------------
// chunk0: fp32 (Af, 3-pass split) OR fp16 (Ah0, 2-pass); chunk1 (optional): fp16 (Ah1)
__global__ __launch_bounds__(256, 2) void gemm_mma(
    const float* __restrict__ Af, const __half* __restrict__ Ah0,
    const __half* __restrict__ Ah1, int sA, int wc0, int nchunks,
    const float* __restrict__ bias, const float* __restrict__ resid,
    const int* __restrict__ mask, int sMask,
    float* __restrict__ outf, __half* __restrict__ outh, int M, int epi)
{
    extern __shared__ char smem[];
    uint32_t sb = s2u(smem);
    int tid = threadIdx.x;
    int wid = tid >> 5, lane = tid & 31;
    int mwarp = wid & 3, nwarp = wid >> 2;
    int row0 = blockIdx.x * 128;
    int pl = blockIdx.y;
    const float* Afp = Af ? (Af + (size_t)pl * sA) : nullptr;
    const __half* Ah0p = Ah0 ? (Ah0 + (size_t)pl * sA) : nullptr;
    const __half* Ah1p = Ah1 ? (Ah1 + (size_t)pl * sA) : nullptr;
    const float* residp = resid ? (resid + (size_t)pl * sA) : nullptr;
    const int* maskp = mask ? (mask + (size_t)pl * sMask) : nullptr;

    float C[2][8][4];
    #pragma unroll
    for (int mt = 0; mt < 2; mt++)
        #pragma unroll
        for (int nt = 0; nt < 8; nt++)
            #pragma unroll
            for (int q = 0; q < 4; q++) C[mt][nt][q] = 0.f;

    int a_row_in16 = (lane & 7) + ((lane >> 3) & 1) * 8;
    int a_kb = (lane >> 4) & 1;
    int b_row_in16 = (lane & 7) + ((lane >> 4) & 1) * 8;
    int b_kb = (lane >> 3) & 1;

    for (int ch = 0; ch < nchunks; ch++) {
        bool cf32 = (ch == 0) && (Af != nullptr);
        for (int s = 0; s < 2; s++) {
            if (cf32) {
                #pragma unroll
                for (int l = 0; l < 8; l++) {
                    int i = l * 256 + tid;
                    int r = i >> 4, c4 = (i & 15) * 4;
                    float4 v = make_float4(0.f, 0.f, 0.f, 0.f);
                    int row = row0 + r;
                    if (row < M)
                        v = *reinterpret_cast<const float4*>(&Afp[(size_t)row * 128 + s * 64 + c4]);
                    uint32_t o = swz(r, c4);
                    *reinterpret_cast<uint2*>(smem + SM_AHI + o) =
                        make_uint2(pack2h(v.x, v.y), pack2h(v.z, v.w));
                    *reinterpret_cast<uint2*>(smem + SM_ALO + o) =
                        make_uint2(pack2h(lopart(v.x), lopart(v.y)),
                                   pack2h(lopart(v.z), lopart(v.w)));
                }
            } else {
                const __half* src = ch ? Ah1p : Ah0p;
                #pragma unroll
                for (int l = 0; l < 8; l++) {
                    int i = l * 256 + tid;
                    int r = i >> 4, c4 = (i & 15) * 4;
                    uint2 v = make_uint2(0u, 0u);
                    int row = row0 + r;
                    if (row < M)
                        v = *reinterpret_cast<const uint2*>(&src[(size_t)row * 128 + s * 64 + c4]);
                    *reinterpret_cast<uint2*>(smem + SM_AHI + swz(r, c4)) = v;
                }
            }
            const uint4* bh = &g_wbuf[wc0 + ch][0][s][0];
            const uint4* bl = &g_wbuf[wc0 + ch][1][s][0];
            #pragma unroll
            for (int l = 0; l < 4; l++) {
                int i = l * 256 + tid;
                *reinterpret_cast<uint4*>(smem + SM_BHI + i * 16) = bh[i];
                *reinterpret_cast<uint4*>(smem + SM_BLO + i * 16) = bl[i];
            }
            __syncthreads();

            #pragma unroll
            for (int k16 = 0; k16 < 4; k16++) {
                uint32_t ahi[2][4], alo[2][4];
                #pragma unroll
                for (int mt = 0; mt < 2; mt++) {
                    int row = mwarp * 32 + mt * 16 + a_row_in16;
                    uint32_t o = (uint32_t)(row * 128 + ((((k16 * 2 + a_kb) ^ row) & 7) << 4));
                    ldsm4(ahi[mt], sb + SM_AHI + o);
                    if (cf32) ldsm4(alo[mt], sb + SM_ALO + o);
                }
                #pragma unroll
                for (int ntp = 0; ntp < 4; ntp++) {
                    int nrow = nwarp * 64 + ntp * 16 + b_row_in16;
                    uint32_t o = (uint32_t)(nrow * 128 + ((((k16 * 2 + b_kb) ^ nrow) & 7) << 4));
                    uint32_t bhi[4], blo[4];
                    ldsm4(bhi, sb + SM_BHI + o);
                    ldsm4(blo, sb + SM_BLO + o);
                    #pragma unroll
                    for (int half = 0; half < 2; half++) {
                        int nt = ntp * 2 + half;
                        #pragma unroll
                        for (int mt = 0; mt < 2; mt++) {
                            mma16816(C[mt][nt], ahi[mt], bhi[half * 2], bhi[half * 2 + 1]);
                            mma16816(C[mt][nt], ahi[mt], blo[half * 2], blo[half * 2 + 1]);
                            if (cf32)
                                mma16816(C[mt][nt], alo[mt], bhi[half * 2], bhi[half * 2 + 1]);
                        }
                    }
                }
            }
            __syncthreads();
        }
    }

    int qrow = lane >> 2;
    int qcol = (lane & 3) * 2;
    #pragma unroll
    for (int mt = 0; mt < 2; mt++) {
        #pragma unroll
        for (int half = 0; half < 2; half++) {
            int row = row0 + mwarp * 32 + mt * 16 + qrow + half * 8;
            if (row >= M) continue;
            bool mk = (epi == EPI_MASKBIAS) ? (maskp[row] > 0) : false;
            #pragma unroll
            for (int nt = 0; nt < 8; nt++) {
                int col = nwarp * 64 + nt * 8 + qcol;
                float v0 = C[mt][nt][half * 2 + 0];
                float v1 = C[mt][nt][half * 2 + 1];
                float o0, o1;
                if (epi == EPI_PLAIN) { o0 = v0; o1 = v1; }
                else if (epi == EPI_RELU) {
                    o0 = fmaxf(v0 + bias[col], 0.f);
                    o1 = fmaxf(v1 + bias[col + 1], 0.f);
                } else if (epi == EPI_RESRELU) {
                    float2 rr = *reinterpret_cast<const float2*>(&residp[(size_t)row * 128 + col]);
                    o0 = rr.x + fmaxf(v0 + bias[col], 0.f);
                    o1 = rr.y + fmaxf(v1 + bias[col + 1], 0.f);
                } else {
                    o0 = mk ? (v0 + bias[col]) : 0.f;
                    o1 = mk ? (v1 + bias[col + 1]) : 0.f;
                }
                if (outh) {
                    __half2 hv = __floats2half2_rn(o0, o1);
                    *reinterpret_cast<__half2*>(&outh[(size_t)pl * sA + (size_t)row * 128 + col]) = hv;
                } else {
                    *reinterpret_cast<float2*>(&outf[(size_t)pl * sA + (size_t)row * 128 + col]) =
                        make_float2(o0, o1);
                }
            }
        }
    }
}

// ---------------- dual-output GEMM: fp32 A staged once (3-pass), two weight sets, fp16 out ----------------
__global__ __launch_bounds__(256, 2) void gemm_dual(
    const float* __restrict__ A, int sA, int wc0, int wc1,
    __half* __restrict__ out0, __half* __restrict__ out1, int M)
{
    extern __shared__ char smem[];
    uint32_t sb = s2u(smem);
    int tid = threadIdx.x;
    int wid = tid >> 5, lane = tid & 31;
    int mwarp = wid & 3, nwarp = wid >> 2;
    int row0 = blockIdx.x * 128;
    int pl = blockIdx.y;
    const float* Ap = A + (size_t)pl * sA;
    __half* o0 = out0 + (size_t)pl * sA;
    __half* o1 = out1 + (size_t)pl * sA;

    int a_row_in16 = (lane & 7) + ((lane >> 3) & 1) * 8;
    int a_kb = (lane >> 4) & 1;
    int b_row_in16 = (lane & 7) + ((lane >> 4) & 1) * 8;
    int b_kb = (lane >> 3) & 1;

    #pragma unroll
    for (int l = 0; l < 16; l++) {
        int i = l * 256 + tid;
        int r = i >> 5, c4 = (i & 31) * 4;
        int s = c4 >> 6, k = c4 & 63;
        float4 v = make_float4(0.f, 0.f, 0.f, 0.f);
        int row = row0 + r;
        if (row < M)
            v = *reinterpret_cast<const float4*>(&Ap[(size_t)row * 128 + c4]);
        uint32_t o = s * 16384 + swz(r, k);
        *reinterpret_cast<uint2*>(smem + DU_AHI + o) =
            make_uint2(pack2h(v.x, v.y), pack2h(v.z, v.w));
        *reinterpret_cast<uint2*>(smem + DU_ALO + o) =
            make_uint2(pack2h(lopart(v.x), lopart(v.y)), pack2h(lopart(v.z), lopart(v.w)));
    }

    int qrow = lane >> 2;
    int qcol = (lane & 3) * 2;

    #pragma unroll
    for (int w = 0; w < 2; w++) {
        int wc = w ? wc1 : wc0;
        __half* op = w ? o1 : o0;
        float C[2][8][4];
        #pragma unroll
        for (int mt = 0; mt < 2; mt++)
            #pragma unroll
            for (int nt = 0; nt < 8; nt++)
                #pragma unroll
                for (int q = 0; q < 4; q++) C[mt][nt][q] = 0.f;

        for (int s = 0; s < 2; s++) {
            __syncthreads();
            const uint4* bh = &g_wbuf[wc][0][s][0];
            const uint4* bl = &g_wbuf[wc][1][s][0];
            #pragma unroll
            for (int l = 0; l < 4; l++) {
                int i = l * 256 + tid;
                *reinterpret_cast<uint4*>(smem + DU_BHI + i * 16) = bh[i];
                *reinterpret_cast<uint4*>(smem + DU_BLO + i * 16) = bl[i];
            }
            __syncthreads();

            uint32_t abase = (uint32_t)(s * 16384);
            #pragma unroll
            for (int k16 = 0; k16 < 4; k16++) {
                uint32_t ahi[2][4], alo[2][4];
                #pragma unroll
                for (int mt = 0; mt < 2; mt++) {
                    int row = mwarp * 32 + mt * 16 + a_row_in16;
                    uint32_t o = (uint32_t)(row * 128 + ((((k16 * 2 + a_kb) ^ row) & 7) << 4));
                    ldsm4(ahi[mt], sb + DU_AHI + abase + o);
                    ldsm4(alo[mt], sb + DU_ALO + abase + o);
                }
                #pragma unroll
                for (int ntp = 0; ntp < 4; ntp++) {
                    int nrow = nwarp * 64 + ntp * 16 + b_row_in16;
                    uint32_t o = (uint32_t)(nrow * 128 + ((((k16 * 2 + b_kb) ^ nrow) & 7) << 4));
                    uint32_t bhi[4], blo[4];
                    ldsm4(bhi, sb + DU_BHI + o);
                    ldsm4(blo, sb + DU_BLO + o);
                    #pragma unroll
                    for (int half = 0; half < 2; half++) {
                        int nt = ntp * 2 + half;
                        #pragma unroll
                        for (int mt = 0; mt < 2; mt++) {
                            mma16816(C[mt][nt], ahi[mt], bhi[half * 2], bhi[half * 2 + 1]);
                            mma16816(C[mt][nt], ahi[mt], blo[half * 2], blo[half * 2 + 1]);
                            mma16816(C[mt][nt], alo[mt], bhi[half * 2], bhi[half * 2 + 1]);
                        }
                    }
                }
            }
        }

        #pragma unroll
        for (int mt = 0; mt < 2; mt++) {
            #pragma unroll
            for (int half = 0; half < 2; half++) {
                int row = row0 + mwarp * 32 + mt * 16 + qrow + half * 8;
                if (row >= M) continue;
                #pragma unroll
                for (int nt = 0; nt < 8; nt++) {
                    int col = nwarp * 64 + nt * 8 + qcol;
                    *reinterpret_cast<__half2*>(&op[(size_t)row * 128 + col]) =
                        __floats2half2_rn(C[mt][nt][half * 2], C[mt][nt][half * 2 + 1]);
                }
            }
        }
    }
}

// ---------------- CSR build ----------------
__global__ void zero_counts() {
    int i = blockIdx.x * blockDim.x + threadIdx.x;
    if (i < NHIT) {
        #pragma unroll
        for (int p = 0; p < 3; p++) { g_deg[p][i] = 0; g_cb[p][i] = 0; }
    }
    if (i < NSP) {
        #pragma unroll
        for (int p = 0; p < 3; p++) g_cf[p][i] = 0;
    }
}

__global__ void count_all(const int* __restrict__ e0, const int* __restrict__ e1,
                          const int* __restrict__ e2, const int* __restrict__ n0,
                          const int* __restrict__ n1, const int* __restrict__ n2) {
    int p = blockIdx.y;
    const int* e = (p == 0) ? e0 : (p == 1) ? e1 : e2;
    const int* nx = (p == 0) ? n0 : (p == 1) ? n1 : n2;
    int i = blockIdx.x * blockDim.x + threadIdx.x;
    if (i < NEDGE) atomicAdd(&g_deg[p][e[NEDGE + i]], 1);
    if (i < NSP) {
        atomicAdd(&g_cf[p][nx[NSP + i]], 1);
        atomicAdd(&g_cb[p][nx[i]], 1);
    }
}

__global__ void scan_excl_all() {
    int sel = blockIdx.x / 3, p = blockIdx.x % 3;
    const int* in; int* out; int* cur; int n;
    if (sel == 0)      { in = g_deg[p]; out = g_offE[p]; cur = g_curE[p]; n = NHIT; }
    else if (sel == 1) { in = g_cf[p];  out = g_offF[p]; cur = g_curF[p]; n = NSP; }
    else               { in = g_cb[p];  out = g_offB[p]; cur = g_curB[p]; n = NHIT; }
    __shared__ int wsum[32];
    __shared__ int carry;
    int tid = threadIdx.x;
    if (tid == 0) carry = 0;
    __syncthreads();
    for (int base = 0; base < n; base += 1024) {
        int i = base + tid;
        int v = (i < n) ? in[i] : 0;
        int x = v;
        #pragma unroll
        for (int d = 1; d < 32; d <<= 1) {
            int y = __shfl_up_sync(0xffffffffu, x, d);
            if ((tid & 31) >= d) x += y;
        }
        if ((tid & 31) == 31) wsum[tid >> 5] = x;
        __syncthreads();
        if (tid < 32) {
            int s = wsum[tid];
            #pragma unroll
            for (int d = 1; d < 32; d <<= 1) {
                int y = __shfl_up_sync(0xffffffffu, s, d);
                if (tid >= d) s += y;
            }
            wsum[tid] = s;
        }
        __syncthreads();
        int woff = (tid >= 32) ? wsum[(tid >> 5) - 1] : 0;
        int incl = carry + woff + x;
        if (i < n) { out[i] = incl - v; cur[i] = incl - v; }
        __syncthreads();
        if (tid == 1023) carry = incl;
        __syncthreads();
    }
    if (tid == 0) out[n] = carry;
}

__global__ void fill_all(const int* __restrict__ e0, const int* __restrict__ e1,
                         const int* __restrict__ e2, const int* __restrict__ n0,
                         const int* __restrict__ n1, const int* __restrict__ n2) {
    int p = blockIdx.y;
    const int* e = (p == 0) ? e0 : (p == 1) ? e1 : e2;
    const int* nx = (p == 0) ? n0 : (p == 1) ? n1 : n2;
    int i = blockIdx.x * blockDim.x + threadIdx.x;
    if (i < NEDGE) {
        int dst = e[NEDGE + i];
        g_csrE[p][atomicAdd(&g_curE[p][dst], 1)] = e[i];
    }
    if (i < NSP) {
        int s = nx[NSP + i];
        g_csrF[p][atomicAdd(&g_curF[p][s], 1)] = nx[i];
        int h = nx[i];
        g_csrB[p][atomicAdd(&g_curB[p][h], 1)] = nx[NSP + i];
    }
}

// ---------------- encoder (plane-batched) ----------------
__global__ void encoder_k(const float* __restrict__ x0, const float* __restrict__ x1,
                          const float* __restrict__ x2, const float* __restrict__ W,
                          const float* __restrict__ b, float* __restrict__ hbase) {
    int p = blockIdx.y;
    const float* x = (p == 0) ? x0 : (p == 1) ? x1 : x2;
    float* h = hbase + (size_t)p * PSTRIDE;
    int idx = blockIdx.x * blockDim.x + threadIdx.x;
    if (idx >= NHIT * HD) return;
    int n = idx >> 7, j = idx & 127;
    float acc = b[j];
    #pragma unroll
    for (int k = 0; k < 4; k++) acc = fmaf(x[n * 4 + k], W[k * HD + j], acc);
    h[idx] = fmaxf(acc, 0.f);
}

// ---------------- planar edge aggregation (fp16 in/out, warp per node) ----------------
__global__ void planar_agg(const float* __restrict__ b1) {
    int p = blockIdx.y;
    int warp = (blockIdx.x * blockDim.x + threadIdx.x) >> 5;
    if (warp >= NHIT) return;
    int lane = threadIdx.x & 31;
    int n = warp;
    uint2 ar = *reinterpret_cast<const uint2*>(&g_A[p][(size_t)n * HD + lane * 4]);
    float2 a01 = __half22float2(*reinterpret_cast<__half2*>(&ar.x));
    float2 a23 = __half22float2(*reinterpret_cast<__half2*>(&ar.y));
    float4 bb = *reinterpret_cast<const float4*>(&b1[lane * 4]);
    int s = g_offE[p][n], e = g_offE[p][n + 1];
    float4 acc = make_float4(0.f, 0.f, 0.f, 0.f);
    for (int i = s; i < e; i++) {
        int src = g_csrE[p][i];
        uint2 br = *reinterpret_cast<const uint2*>(&g_B[p][(size_t)src * HD + lane * 4]);
        float2 b01 = __half22float2(*reinterpret_cast<__half2*>(&br.x));
        float2 b23 = __half22float2(*reinterpret_cast<__half2*>(&br.y));
        acc.x += fmaxf(a01.x + b01.x + bb.x, 0.f);
        acc.y += fmaxf(a01.y + b01.y + bb.y, 0.f);
        acc.z += fmaxf(a23.x + b23.x + bb.z, 0.f);
        acc.w += fmaxf(a23.y + b23.y + bb.w, 0.f);
    }
    float inv = (e > s) ? 1.f / (float)(e - s) : 0.f;
    uint2 o;
    *reinterpret_cast<__half2*>(&o.x) = __floats2half2_rn(acc.x * inv, acc.y * inv);
    *reinterpret_cast<__half2*>(&o.y) = __floats2half2_rn(acc.z * inv, acc.w * inv);
    *reinterpret_cast<uint2*>(&g_mr[p][(size_t)n * HD + lane * 4]) = o;
}

// ---------------- nexus forward: h(fp32) -> spsum(fp16) ----------------
__global__ void nexus_fwd(const float* __restrict__ hbase) {
    int warp = (blockIdx.x * blockDim.x + threadIdx.x) >> 5;
    if (warp >= NSP) return;
    int lane = threadIdx.x & 31;
    int s = warp;
    float4 tot = make_float4(0.f, 0.f, 0.f, 0.f);
    #pragma unroll
    for (int p = 0; p < 3; p++) {
        const float* h = hbase + (size_t)p * PSTRIDE;
        int st = g_offF[p][s], en = g_offF[p][s + 1];
        float4 acc = make_float4(0.f, 0.f, 0.f, 0.f);
        for (int i = st; i < en; i++) {
            int hit = g_csrF[p][i];
            float4 v = *reinterpret_cast<const float4*>(&h[(size_t)hit * HD + lane * 4]);
            acc.x += v.x; acc.y += v.y; acc.z += v.z; acc.w += v.w;
        }
        if (en > st) {
            float inv = 1.f / (float)(en - st);
            tot.x += acc.x * inv; tot.y += acc.y * inv;
            tot.z += acc.z * inv; tot.w += acc.w * inv;
        }
    }
    uint2 o;
    *reinterpret_cast<__half2*>(&o.x) = __floats2half2_rn(tot.x, tot.y);
    *reinterpret_cast<__half2*>(&o.y) = __floats2half2_rn(tot.z, tot.w);
    *reinterpret_cast<uint2*>(&g_spsum[(size_t)s * HD + lane * 4]) = o;
}

// ---------------- nexus backward: sp(fp16) -> back(fp16) ----------------
__global__ void nexus_back() {
    int p = blockIdx.y;
    int warp = (blockIdx.x * blockDim.x + threadIdx.x) >> 5;
    if (warp >= NHIT) return;
    int lane = threadIdx.x & 31;
    int n = warp;
    int st = g_offB[p][n], en = g_offB[p][n + 1];
    float4 acc = make_float4(0.f, 0.f, 0.f, 0.f);
    for (int i = st; i < en; i++) {
        int spi = g_csrB[p][i];
        uint2 vr = *reinterpret_cast<const uint2*>(&g_sp[(size_t)spi * HD + lane * 4]);
        float2 v01 = __half22float2(*reinterpret_cast<__half2*>(&vr.x));
        float2 v23 = __half22float2(*reinterpret_cast<__half2*>(&vr.y));
        acc.x += v01.x; acc.y += v01.y; acc.z += v23.x; acc.w += v23.y;
    }
    float inv = (en > st) ? 1.f / (float)(en - st) : 0.f;
    uint2 o;
    *reinterpret_cast<__half2*>(&o.x) = __floats2half2_rn(acc.x * inv, acc.y * inv);
    *reinterpret_cast<__half2*>(&o.y) = __floats2half2_rn(acc.z * inv, acc.w * inv);
    *reinterpret_cast<uint2*>(&g_back[p][(size_t)n * HD + lane * 4]) = o;
}

// ---------------- decoder (plane-batched) ----------------
__global__ void decoder_k(const float* __restrict__ hbase, const float* __restrict__ Wsem,
                          const float* __restrict__ bsem, float* __restrict__ out) {
    int p = blockIdx.y;
    const float* h = hbase + (size_t)p * PSTRIDE;
    float* o = out + (size_t)p * NHIT * NCLASS;
    int warp = (blockIdx.x * blockDim.x + threadIdx.x) >> 5;
    if (warp >= NHIT) return;
    int lane = threadIdx.x & 31;
    int n = warp;
    float hv[4];
    #pragma unroll
    for (int t = 0; t < 4; t++) hv[t] = h[(size_t)n * HD + lane + t * 32];
    #pragma unroll
    for (int c = 0; c < NCLASS; c++) {
        float s = 0.f;
        #pragma unroll
        for (int t = 0; t < 4; t++) s = fmaf(hv[t], Wsem[(lane + t * 32) * NCLASS + c], s);
        #pragma unroll
        for (int d = 16; d > 0; d >>= 1) s += __shfl_down_sync(0xffffffffu, s, d);
        if (lane == 0) o[n * NCLASS + c] = s + bsem[c];
    }
}

// ---------------- host ----------------
extern "C" void kernel_launch(void* const* d_in, const int* in_sizes, int n_in,
                              void* d_out, int out_size) {
    int xi[3], ei[3], ni[3];
    if (in_sizes[1] == 2 * NEDGE) {
        for (int p = 0; p < 3; p++) { xi[p] = 3 * p; ei[p] = 3 * p + 1; ni[p] = 3 * p + 2; }
    } else {
        for (int p = 0; p < 3; p++) { xi[p] = p; ei[p] = 3 + p; ni[p] = 6 + p; }
    }
    const float* x[3]; const int* edge[3]; const int* nexus[3];
    for (int p = 0; p < 3; p++) {
        x[p] = (const float*)d_in[xi[p]];
        edge[p] = (const int*)d_in[ei[p]];
        nexus[p] = (const int*)d_in[ni[p]];
    }
    const float* W_enc  = (const float*)d_in[9];
    const float* b_enc  = (const float*)d_in[10];
    const float* W_msg1 = (const float*)d_in[11];
    const float* b_msg1 = (const float*)d_in[12];
    const float* W_msg2 = (const float*)d_in[13];
    const float* b_msg2 = (const float*)d_in[14];
    const float* W_upd  = (const float*)d_in[15];
    const float* b_upd  = (const float*)d_in[16];
    const float* W_sp   = (const float*)d_in[17];
    const float* b_sp   = (const float*)d_in[18];
    const float* W_nx   = (const float*)d_in[19];
    const float* b_nx   = (const float*)d_in[20];
    const float* W_sem  = (const float*)d_in[21];
    const float* b_sem  = (const float*)d_in[22];

    float* ph; int* pdeg;
    __half *pA, *pB, *pmr, *pagg, *pspsum, *psp, *pback;
    cudaGetSymbolAddress((void**)&ph, g_h);
    cudaGetSymbolAddress((void**)&pA, g_A);
    cudaGetSymbolAddress((void**)&pB, g_B);
    cudaGetSymbolAddress((void**)&pmr, g_mr);
    cudaGetSymbolAddress((void**)&pagg, g_agg);
    cudaGetSymbolAddress((void**)&pspsum, g_spsum);
    cudaGetSymbolAddress((void**)&psp, g_sp);
    cudaGetSymbolAddress((void**)&pback, g_back);
    cudaGetSymbolAddress((void**)&pdeg, g_deg);

    cudaFuncSetAttribute(gemm_mma, cudaFuncAttributeMaxDynamicSharedMemorySize, SM_TOTAL);
    cudaFuncSetAttribute(gemm_dual, cudaFuncAttributeMaxDynamicSharedMemorySize, DU_TOTAL);

    float* h0 = ph;
    float* h1 = ph + (size_t)3 * PSTRIDE;

    const int T = 256;
    dim3 gG3((NHIT + 127) / 128, 3);
    dim3 gG1((NHIT + 127) / 128, 1);
    dim3 gW3((NHIT * 32 + T - 1) / T, 3);
    int gW1 = (NSP * 32 + T - 1) / T;
    dim3 gE((NHIT * HD + T - 1) / T, 3);

    // --- CSR build ---
    zero_counts<<<(NHIT + T - 1) / T, T>>>();
    dim3 gCnt((NEDGE + T - 1) / T, 3);
    count_all<<<gCnt, T>>>(edge[0], edge[1], edge[2], nexus[0], nexus[1], nexus[2]);
    scan_excl_all<<<9, 1024>>>();
    fill_all<<<gCnt, T>>>(edge[0], edge[1], edge[2], nexus[0], nexus[1], nexus[2]);

    // --- weight prep (0=W1top 1=W1bot 2=Wmsg2 3=WupdT 4=WupdB 5=Wsp 6=WnxT 7=WnxB) ---
    prep_w<<<256, 256>>>(W_msg1, W_msg1 + 128 * 128, W_msg2,
                         W_upd, W_upd + 128 * 128, W_sp,
                         W_nx, W_nx + 128 * 128);

    // --- encoder ---
    encoder_k<<<gE, T>>>(x[0], x[1], x[2], W_enc, b_enc, h0);

    for (int it = 0; it < 3; it++) {
        // planar convolution
        gemm_dual<<<gG3, T, DU_TOTAL>>>(h0, PSTRIDE, 0, 1, pA, pB, NHIT);
        planar_agg<<<gW3, T>>>(b_msg1);
        gemm_mma<<<gG3, T, SM_TOTAL>>>(nullptr, pmr, nullptr, PSTRIDE, 2, 1, b_msg2,
                                       nullptr, pdeg, NHIT, nullptr, pagg, NHIT, EPI_MASKBIAS);
        gemm_mma<<<gG3, T, SM_TOTAL>>>(h0, nullptr, pagg, PSTRIDE, 3, 2, b_upd,
                                       h0, nullptr, 0, h1, nullptr, NHIT, EPI_RESRELU);
        // nexus convolution
        nexus_fwd<<<gW1, T>>>(h1);
        gemm_mma<<<gG1, T, SM_TOTAL>>>(nullptr, pspsum, nullptr, 0, 5, 1, b_sp,
                                       nullptr, nullptr, 0, nullptr, psp, NSP, EPI_RELU);
        nexus_back<<<gW3, T>>>();
        gemm_mma<<<gG3, T, SM_TOTAL>>>(h1, nullptr, pback, PSTRIDE, 6, 2, b_nx,
                                       h1, nullptr, 0, h0, nullptr, NHIT, EPI_RESRELU);
    }

    decoder_k<<<gW3, T>>>(h0, W_sem, b_sem, (float*)d_out);
}

// round 7
// speedup vs baseline: 2.7724x; 1.0031x over previous
#include <cuda_runtime.h>
#include <cuda_fp16.h>
#include <cstdint>

#define NHIT 30000
#define NEDGE 90000
#define NSP 30000
#define HD 128
#define NCLASS 5
#define PSTRIDE (NHIT * HD)

// ---------------- device scratch ----------------
__device__ float g_h[2][3][NHIT * HD];          // fp32 state (residual path)
__device__ __half g_h16[2][3][NHIT * HD];       // fp16 shadow of h (GEMM A operand)
__device__ __half g_A[3][NHIT * HD];
__device__ __half g_B[3][NHIT * HD];
__device__ __half g_mr[3][NHIT * HD];
__device__ __half g_spsum[NSP * HD];
__device__ __half g_sp[NSP * HD];
__device__ __half g_back[3][NHIT * HD];
__device__ float g_wcomb[HD * HD];              // W_msg2 @ W_upd_bottom (fp32)
__device__ float g_b2c[HD];                     // b_msg2 @ W_upd_bottom

// prepped weights: 7 chunks x {hi,lo} x 2 k-stages x (128n x 64k fp16, swizzled)
__device__ uint4 g_wbuf[7][2][2][1024];

__device__ int g_deg[3][NHIT];
__device__ int g_cf[3][NSP];
__device__ int g_cb[3][NHIT];
__device__ int g_offE[3][NHIT + 1];
__device__ int g_offF[3][NSP + 1];
__device__ int g_offB[3][NHIT + 1];
__device__ int g_csrE[3][NEDGE];
__device__ int g_csrF[3][NSP];
__device__ int g_csrB[3][NSP];
__device__ int g_curE[3][NHIT];
__device__ int g_curF[3][NSP];
__device__ int g_curB[3][NHIT];

enum { EPI_RELU = 1, EPI_RESRELU = 2, EPI_RESRELU_DEG = 4 };

// ---------------- helpers ----------------
__device__ __forceinline__ uint32_t s2u(const void* p) {
    return (uint32_t)__cvta_generic_to_shared(p);
}
__device__ __forceinline__ uint32_t pack2h(float a, float b) {
    __half2 t = __floats2half2_rn(a, b);
    return *reinterpret_cast<uint32_t*>(&t);
}
__device__ __forceinline__ float lopart(float v) {
    return v - __half2float(__float2half(v));
}
__device__ __forceinline__ uint32_t swz(int row, int k) {
    return (uint32_t)(row * 128 + ((((k >> 3) ^ row) & 7) << 4) + (k & 7) * 2);
}
__device__ __forceinline__ void ldsm4(uint32_t* r, uint32_t addr) {
    asm volatile("ldmatrix.sync.aligned.m8n8.x4.shared.b16 {%0,%1,%2,%3}, [%4];"
                 : "=r"(r[0]), "=r"(r[1]), "=r"(r[2]), "=r"(r[3]) : "r"(addr));
}
__device__ __forceinline__ void mma16816(float* c, const uint32_t* a, uint32_t b0, uint32_t b1) {
    asm volatile(
        "mma.sync.aligned.m16n8k16.row.col.f32.f16.f16.f32 "
        "{%0,%1,%2,%3}, {%4,%5,%6,%7}, {%8,%9}, {%0,%1,%2,%3};"
        : "+f"(c[0]), "+f"(c[1]), "+f"(c[2]), "+f"(c[3])
        : "r"(a[0]), "r"(a[1]), "r"(a[2]), "r"(a[3]), "r"(b0), "r"(b1));
}

// gemm_mma smem (48KB): A hi only + B hi/lo
#define SM_A 0
#define SM_BHI 16384
#define SM_BLO 32768
#define SM_TOTAL 49152
// gemm_dual smem (64KB): A both stages + B hi/lo
#define DU_A 0
#define DU_BHI 32768
#define DU_BLO 49152
#define DU_TOTAL 65536

// ---------------- weight combine: g_wcomb = W_msg2 @ W_upd_bot; g_b2c = b_msg2 @ W_upd_bot ----------------
__global__ void combine_w(const float* __restrict__ W2, const float* __restrict__ Wub,
                          const float* __restrict__ b2) {
    int n = threadIdx.x;
    int k = blockIdx.x;
    if (k < 128) {
        float s = 0.f;
        #pragma unroll 8
        for (int j = 0; j < 128; j++) s = fmaf(W2[k * 128 + j], Wub[j * 128 + n], s);
        g_wcomb[k * 128 + n] = s;
    } else {
        float s = 0.f;
        #pragma unroll 8
        for (int j = 0; j < 128; j++) s = fmaf(b2[j], Wub[j * 128 + n], s);
        g_b2c[n] = s;
    }
}

// ---------------- weight prep: transpose + fp16 hi/lo + swizzle (7 chunks) ----------------
__global__ void prep_w(const float* w0, const float* w1, const float* w2,
                       const float* w3, const float* w4, const float* w5,
                       const float* w6) {
    int id = blockIdx.x * blockDim.x + threadIdx.x;   // 57344 total
    if (id >= 7 * 8192) return;
    int c = id >> 13;
    int rem = id & 8191;
    int s = rem >> 12;
    int rem2 = rem & 4095;
    int n = rem2 >> 5;
    int kp = (rem2 & 31) * 2;
    const float* Wc = (c == 0) ? w0 : (c == 1) ? w1 : (c == 2) ? w2 : (c == 3) ? w3
                    : (c == 4) ? w4 : (c == 5) ? w5 : w6;
    float v0 = Wc[(s * 64 + kp) * 128 + n];
    float v1 = Wc[(s * 64 + kp + 1) * 128 + n];
    uint32_t o = swz(n, kp);
    *reinterpret_cast<uint32_t*>((char*)&g_wbuf[c][0][s][0] + o) = pack2h(v0, v1);
    *reinterpret_cast<uint32_t*>((char*)&g_wbuf[c][1][s][0] + o) = pack2h(lopart(v0), lopart(v1));
}

// ---------------- HMMA 2-pass GEMM (fp16 A, plane-batched) ----------------
__global__ __launch_bounds__(256, 2) void gemm_mma(
    const __half* __restrict__ Ah0, const __half* __restrict__ Ah1,
    int sA, int wc0, int nchunks,
    const float* __restrict__ bias, const float* __restrict__ bias2,
    const int* __restrict__ mask, int sMask,
    const float* __restrict__ resid,
    float* __restrict__ outf, __half* __restrict__ outh, int M, int epi)
{
    extern __shared__ char smem[];
    uint32_t sb = s2u(smem);
    int tid = threadIdx.x;
    int wid = tid >> 5, lane = tid & 31;
    int mwarp = wid & 3, nwarp = wid >> 2;
    int row0 = blockIdx.x * 128;
    int pl = blockIdx.y;
    const __half* Ah0p = Ah0 + (size_t)pl * sA;
    const __half* Ah1p = Ah1 ? (Ah1 + (size_t)pl * sA) : nullptr;
    const float* residp = resid ? (resid + (size_t)pl * sA) : nullptr;
    const int* maskp = mask ? (mask + (size_t)pl * sMask) : nullptr;

    float C[2][8][4];
    #pragma unroll
    for (int mt = 0; mt < 2; mt++)
        #pragma unroll
        for (int nt = 0; nt < 8; nt++)
            #pragma unroll
            for (int q = 0; q < 4; q++) C[mt][nt][q] = 0.f;

    int a_row_in16 = (lane & 7) + ((lane >> 3) & 1) * 8;
    int a_kb = (lane >> 4) & 1;
    int b_row_in16 = (lane & 7) + ((lane >> 4) & 1) * 8;
    int b_kb = (lane >> 3) & 1;

    for (int ch = 0; ch < nchunks; ch++) {
        const __half* src = ch ? Ah1p : Ah0p;
        for (int s = 0; s < 2; s++) {
            #pragma unroll
            for (int l = 0; l < 8; l++) {
                int i = l * 256 + tid;
                int r = i >> 4, c4 = (i & 15) * 4;
                uint2 v = make_uint2(0u, 0u);
                int row = row0 + r;
                if (row < M)
                    v = *reinterpret_cast<const uint2*>(&src[(size_t)row * 128 + s * 64 + c4]);
                *reinterpret_cast<uint2*>(smem + SM_A + swz(r, c4)) = v;
            }
            const uint4* bh = &g_wbuf[wc0 + ch][0][s][0];
            const uint4* bl = &g_wbuf[wc0 + ch][1][s][0];
            #pragma unroll
            for (int l = 0; l < 4; l++) {
                int i = l * 256 + tid;
                *reinterpret_cast<uint4*>(smem + SM_BHI + i * 16) = bh[i];
                *reinterpret_cast<uint4*>(smem + SM_BLO + i * 16) = bl[i];
            }
            __syncthreads();

            #pragma unroll
            for (int k16 = 0; k16 < 4; k16++) {
                uint32_t a[2][4];
                #pragma unroll
                for (int mt = 0; mt < 2; mt++) {
                    int row = mwarp * 32 + mt * 16 + a_row_in16;
                    uint32_t o = (uint32_t)(row * 128 + ((((k16 * 2 + a_kb) ^ row) & 7) << 4));
                    ldsm4(a[mt], sb + SM_A + o);
                }
                #pragma unroll
                for (int ntp = 0; ntp < 4; ntp++) {
                    int nrow = nwarp * 64 + ntp * 16 + b_row_in16;
                    uint32_t o = (uint32_t)(nrow * 128 + ((((k16 * 2 + b_kb) ^ nrow) & 7) << 4));
                    uint32_t bhi[4], blo[4];
                    ldsm4(bhi, sb + SM_BHI + o);
                    ldsm4(blo, sb + SM_BLO + o);
                    #pragma unroll
                    for (int half = 0; half < 2; half++) {
                        int nt = ntp * 2 + half;
                        #pragma unroll
                        for (int mt = 0; mt < 2; mt++) {
                            mma16816(C[mt][nt], a[mt], bhi[half * 2], bhi[half * 2 + 1]);
                            mma16816(C[mt][nt], a[mt], blo[half * 2], blo[half * 2 + 1]);
                        }
                    }
                }
            }
            __syncthreads();
        }
    }

    int qrow = lane >> 2;
    int qcol = (lane & 3) * 2;
    #pragma unroll
    for (int mt = 0; mt < 2; mt++) {
        #pragma unroll
        for (int half = 0; half < 2; half++) {
            int row = row0 + mwarp * 32 + mt * 16 + qrow + half * 8;
            if (row >= M) continue;
            bool dg = (epi == EPI_RESRELU_DEG) ? (maskp[row] > 0) : false;
            #pragma unroll
            for (int nt = 0; nt < 8; nt++) {
                int col = nwarp * 64 + nt * 8 + qcol;
                float v0 = C[mt][nt][half * 2 + 0];
                float v1 = C[mt][nt][half * 2 + 1];
                float o0, o1;
                if (epi == EPI_RELU) {
                    o0 = fmaxf(v0 + bias[col], 0.f);
                    o1 = fmaxf(v1 + bias[col + 1], 0.f);
                } else {
                    float e0 = v0 + bias[col], e1 = v1 + bias[col + 1];
                    if (epi == EPI_RESRELU_DEG && dg) { e0 += bias2[col]; e1 += bias2[col + 1]; }
                    float2 rr = *reinterpret_cast<const float2*>(&residp[(size_t)row * 128 + col]);
                    o0 = rr.x + fmaxf(e0, 0.f);
                    o1 = rr.y + fmaxf(e1, 0.f);
                }
                if (outf)
                    *reinterpret_cast<float2*>(&outf[(size_t)pl * sA + (size_t)row * 128 + col]) =
                        make_float2(o0, o1);
                if (outh)
                    *reinterpret_cast<__half2*>(&outh[(size_t)pl * sA + (size_t)row * 128 + col]) =
                        __floats2half2_rn(o0, o1);
            }
        }
    }
}

// ---------------- dual-output GEMM: fp16 A staged once, two weight sets ----------------
__global__ __launch_bounds__(256, 2) void gemm_dual(
    const __half* __restrict__ A, int sA, int wc0, int wc1,
    __half* __restrict__ out0, __half* __restrict__ out1, int M)
{
    extern __shared__ char smem[];
    uint32_t sb = s2u(smem);
    int tid = threadIdx.x;
    int wid = tid >> 5, lane = tid & 31;
    int mwarp = wid & 3, nwarp = wid >> 2;
    int row0 = blockIdx.x * 128;
    int pl = blockIdx.y;
    const __half* Ap = A + (size_t)pl * sA;
    __half* o0 = out0 + (size_t)pl * sA;
    __half* o1 = out1 + (size_t)pl * sA;

    int a_row_in16 = (lane & 7) + ((lane >> 3) & 1) * 8;
    int a_kb = (lane >> 4) & 1;
    int b_row_in16 = (lane & 7) + ((lane >> 4) & 1) * 8;
    int b_kb = (lane >> 3) & 1;

    // stage A (both 64-k halves) once — pure fp16 copy
    #pragma unroll
    for (int l = 0; l < 16; l++) {
        int i = l * 256 + tid;
        int r = i >> 5, c4 = (i & 31) * 4;
        int s = c4 >> 6, k = c4 & 63;
        uint2 v = make_uint2(0u, 0u);
        int row = row0 + r;
        if (row < M)
            v = *reinterpret_cast<const uint2*>(&Ap[(size_t)row * 128 + c4]);
        *reinterpret_cast<uint2*>(smem + DU_A + s * 16384 + swz(r, k)) = v;
    }

    int qrow = lane >> 2;
    int qcol = (lane & 3) * 2;

    #pragma unroll
    for (int w = 0; w < 2; w++) {
        int wc = w ? wc1 : wc0;
        __half* op = w ? o1 : o0;
        float C[2][8][4];
        #pragma unroll
        for (int mt = 0; mt < 2; mt++)
            #pragma unroll
            for (int nt = 0; nt < 8; nt++)
                #pragma unroll
                for (int q = 0; q < 4; q++) C[mt][nt][q] = 0.f;

        for (int s = 0; s < 2; s++) {
            __syncthreads();
            const uint4* bh = &g_wbuf[wc][0][s][0];
            const uint4* bl = &g_wbuf[wc][1][s][0];
            #pragma unroll
            for (int l = 0; l < 4; l++) {
                int i = l * 256 + tid;
                *reinterpret_cast<uint4*>(smem + DU_BHI + i * 16) = bh[i];
                *reinterpret_cast<uint4*>(smem + DU_BLO + i * 16) = bl[i];
            }
            __syncthreads();

            uint32_t abase = (uint32_t)(s * 16384);
            #pragma unroll
            for (int k16 = 0; k16 < 4; k16++) {
                uint32_t a[2][4];
                #pragma unroll
                for (int mt = 0; mt < 2; mt++) {
                    int row = mwarp * 32 + mt * 16 + a_row_in16;
                    uint32_t o = (uint32_t)(row * 128 + ((((k16 * 2 + a_kb) ^ row) & 7) << 4));
                    ldsm4(a[mt], sb + DU_A + abase + o);
                }
                #pragma unroll
                for (int ntp = 0; ntp < 4; ntp++) {
                    int nrow = nwarp * 64 + ntp * 16 + b_row_in16;
                    uint32_t o = (uint32_t)(nrow * 128 + ((((k16 * 2 + b_kb) ^ nrow) & 7) << 4));
                    uint32_t bhi[4], blo[4];
                    ldsm4(bhi, sb + DU_BHI + o);
                    ldsm4(blo, sb + DU_BLO + o);
                    #pragma unroll
                    for (int half = 0; half < 2; half++) {
                        int nt = ntp * 2 + half;
                        #pragma unroll
                        for (int mt = 0; mt < 2; mt++) {
                            mma16816(C[mt][nt], a[mt], bhi[half * 2], bhi[half * 2 + 1]);
                            mma16816(C[mt][nt], a[mt], blo[half * 2], blo[half * 2 + 1]);
                        }
                    }
                }
            }
        }

        #pragma unroll
        for (int mt = 0; mt < 2; mt++) {
            #pragma unroll
            for (int half = 0; half < 2; half++) {
                int row = row0 + mwarp * 32 + mt * 16 + qrow + half * 8;
                if (row >= M) continue;
                #pragma unroll
                for (int nt = 0; nt < 8; nt++) {
                    int col = nwarp * 64 + nt * 8 + qcol;
                    *reinterpret_cast<__half2*>(&op[(size_t)row * 128 + col]) =
                        __floats2half2_rn(C[mt][nt][half * 2], C[mt][nt][half * 2 + 1]);
                }
            }
        }
    }
}

// ---------------- CSR build ----------------
__global__ void zero_counts() {
    int i = blockIdx.x * blockDim.x + threadIdx.x;
    if (i < NHIT) {
        #pragma unroll
        for (int p = 0; p < 3; p++) { g_deg[p][i] = 0; g_cb[p][i] = 0; }
    }
    if (i < NSP) {
        #pragma unroll
        for (int p = 0; p < 3; p++) g_cf[p][i] = 0;
    }
}

__global__ void count_all(const int* __restrict__ e0, const int* __restrict__ e1,
                          const int* __restrict__ e2, const int* __restrict__ n0,
                          const int* __restrict__ n1, const int* __restrict__ n2) {
    int p = blockIdx.y;
    const int* e = (p == 0) ? e0 : (p == 1) ? e1 : e2;
    const int* nx = (p == 0) ? n0 : (p == 1) ? n1 : n2;
    int i = blockIdx.x * blockDim.x + threadIdx.x;
    if (i < NEDGE) atomicAdd(&g_deg[p][e[NEDGE + i]], 1);
    if (i < NSP) {
        atomicAdd(&g_cf[p][nx[NSP + i]], 1);
        atomicAdd(&g_cb[p][nx[i]], 1);
    }
}

__global__ void scan_excl_all() {
    int sel = blockIdx.x / 3, p = blockIdx.x % 3;
    const int* in; int* out; int* cur; int n;
    if (sel == 0)      { in = g_deg[p]; out = g_offE[p]; cur = g_curE[p]; n = NHIT; }
    else if (sel == 1) { in = g_cf[p];  out = g_offF[p]; cur = g_curF[p]; n = NSP; }
    else               { in = g_cb[p];  out = g_offB[p]; cur = g_curB[p]; n = NHIT; }
    __shared__ int wsum[32];
    __shared__ int carry;
    int tid = threadIdx.x;
    if (tid == 0) carry = 0;
    __syncthreads();
    for (int base = 0; base < n; base += 1024) {
        int i = base + tid;
        int v = (i < n) ? in[i] : 0;
        int x = v;
        #pragma unroll
        for (int d = 1; d < 32; d <<= 1) {
            int y = __shfl_up_sync(0xffffffffu, x, d);
            if ((tid & 31) >= d) x += y;
        }
        if ((tid & 31) == 31) wsum[tid >> 5] = x;
        __syncthreads();
        if (tid < 32) {
            int s = wsum[tid];
            #pragma unroll
            for (int d = 1; d < 32; d <<= 1) {
                int y = __shfl_up_sync(0xffffffffu, s, d);
                if (tid >= d) s += y;
            }
            wsum[tid] = s;
        }
        __syncthreads();
        int woff = (tid >= 32) ? wsum[(tid >> 5) - 1] : 0;
        int incl = carry + woff + x;
        if (i < n) { out[i] = incl - v; cur[i] = incl - v; }
        __syncthreads();
        if (tid == 1023) carry = incl;
        __syncthreads();
    }
    if (tid == 0) out[n] = carry;
}

__global__ void fill_all(const int* __restrict__ e0, const int* __restrict__ e1,
                         const int* __restrict__ e2, const int* __restrict__ n0,
                         const int* __restrict__ n1, const int* __restrict__ n2) {
    int p = blockIdx.y;
    const int* e = (p == 0) ? e0 : (p == 1) ? e1 : e2;
    const int* nx = (p == 0) ? n0 : (p == 1) ? n1 : n2;
    int i = blockIdx.x * blockDim.x + threadIdx.x;
    if (i < NEDGE) {
        int dst = e[NEDGE + i];
        g_csrE[p][atomicAdd(&g_curE[p][dst], 1)] = e[i];
    }
    if (i < NSP) {
        int s = nx[NSP + i];
        g_csrF[p][atomicAdd(&g_curF[p][s], 1)] = nx[i];
        int h = nx[i];
        g_csrB[p][atomicAdd(&g_curB[p][h], 1)] = nx[NSP + i];
    }
}

// ---------------- encoder (writes fp32 + fp16 shadow) ----------------
__global__ void encoder_k(const float* __restrict__ x0, const float* __restrict__ x1,
                          const float* __restrict__ x2, const float* __restrict__ W,
                          const float* __restrict__ b, float* __restrict__ hbase,
                          __half* __restrict__ h16base) {
    int p = blockIdx.y;
    const float* x = (p == 0) ? x0 : (p == 1) ? x1 : x2;
    int idx = blockIdx.x * blockDim.x + threadIdx.x;
    if (idx >= NHIT * HD) return;
    int n = idx >> 7, j = idx & 127;
    float acc = b[j];
    #pragma unroll
    for (int k = 0; k < 4; k++) acc = fmaf(x[n * 4 + k], W[k * HD + j], acc);
    acc = fmaxf(acc, 0.f);
    hbase[(size_t)p * PSTRIDE + idx] = acc;
    h16base[(size_t)p * PSTRIDE + idx] = __float2half(acc);
}

// ---------------- planar edge aggregation ----------------
__global__ void planar_agg(const float* __restrict__ b1) {
    int p = blockIdx.y;
    int warp = (blockIdx.x * blockDim.x + threadIdx.x) >> 5;
    if (warp >= NHIT) return;
    int lane = threadIdx.x & 31;
    int n = warp;
    uint2 ar = *reinterpret_cast<const uint2*>(&g_A[p][(size_t)n * HD + lane * 4]);
    float2 a01 = __half22float2(*reinterpret_cast<__half2*>(&ar.x));
    float2 a23 = __half22float2(*reinterpret_cast<__half2*>(&ar.y));
    float4 bb = *reinterpret_cast<const float4*>(&b1[lane * 4]);
    int s = g_offE[p][n], e = g_offE[p][n + 1];
    float4 acc = make_float4(0.f, 0.f, 0.f, 0.f);
    for (int i = s; i < e; i++) {
        int src = g_csrE[p][i];
        uint2 br = *reinterpret_cast<const uint2*>(&g_B[p][(size_t)src * HD + lane * 4]);
        float2 b01 = __half22float2(*reinterpret_cast<__half2*>(&br.x));
        float2 b23 = __half22float2(*reinterpret_cast<__half2*>(&br.y));
        acc.x += fmaxf(a01.x + b01.x + bb.x, 0.f);
        acc.y += fmaxf(a01.y + b01.y + bb.y, 0.f);
        acc.z += fmaxf(a23.x + b23.x + bb.z, 0.f);
        acc.w += fmaxf(a23.y + b23.y + bb.w, 0.f);
    }
    float inv = (e > s) ? 1.f / (float)(e - s) : 0.f;
    uint2 o;
    *reinterpret_cast<__half2*>(&o.x) = __floats2half2_rn(acc.x * inv, acc.y * inv);
    *reinterpret_cast<__half2*>(&o.y) = __floats2half2_rn(acc.z * inv, acc.w * inv);
    *reinterpret_cast<uint2*>(&g_mr[p][(size_t)n * HD + lane * 4]) = o;
}

// ---------------- nexus forward: h16 -> spsum(fp16) ----------------
__global__ void nexus_fwd(const __half* __restrict__ h16base) {
    int warp = (blockIdx.x * blockDim.x + threadIdx.x) >> 5;
    if (warp >= NSP) return;
    int lane = threadIdx.x & 31;
    int s = warp;
    float4 tot = make_float4(0.f, 0.f, 0.f, 0.f);
    #pragma unroll
    for (int p = 0; p < 3; p++) {
        const __half* h = h16base + (size_t)p * PSTRIDE;
        int st = g_offF[p][s], en = g_offF[p][s + 1];
        float4 acc = make_float4(0.f, 0.f, 0.f, 0.f);
        for (int i = st; i < en; i++) {
            int hit = g_csrF[p][i];
            uint2 vr = *reinterpret_cast<const uint2*>(&h[(size_t)hit * HD + lane * 4]);
            float2 v01 = __half22float2(*reinterpret_cast<__half2*>(&vr.x));
            float2 v23 = __half22float2(*reinterpret_cast<__half2*>(&vr.y));
            acc.x += v01.x; acc.y += v01.y; acc.z += v23.x; acc.w += v23.y;
        }
        if (en > st) {
            float inv = 1.f / (float)(en - st);
            tot.x += acc.x * inv; tot.y += acc.y * inv;
            tot.z += acc.z * inv; tot.w += acc.w * inv;
        }
    }
    uint2 o;
    *reinterpret_cast<__half2*>(&o.x) = __floats2half2_rn(tot.x, tot.y);
    *reinterpret_cast<__half2*>(&o.y) = __floats2half2_rn(tot.z, tot.w);
    *reinterpret_cast<uint2*>(&g_spsum[(size_t)s * HD + lane * 4]) = o;
}

// ---------------- nexus backward ----------------
__global__ void nexus_back() {
    int p = blockIdx.y;
    int warp = (blockIdx.x * blockDim.x + threadIdx.x) >> 5;
    if (warp >= NHIT) return;
    int lane = threadIdx.x & 31;
    int n = warp;
    int st = g_offB[p][n], en = g_offB[p][n + 1];
    float4 acc = make_float4(0.f, 0.f, 0.f, 0.f);
    for (int i = st; i < en; i++) {
        int spi = g_csrB[p][i];
        uint2 vr = *reinterpret_cast<const uint2*>(&g_sp[(size_t)spi * HD + lane * 4]);
        float2 v01 = __half22float2(*reinterpret_cast<__half2*>(&vr.x));
        float2 v23 = __half22float2(*reinterpret_cast<__half2*>(&vr.y));
        acc.x += v01.x; acc.y += v01.y; acc.z += v23.x; acc.w += v23.y;
    }
    float inv = (en > st) ? 1.f / (float)(en - st) : 0.f;
    uint2 o;
    *reinterpret_cast<__half2*>(&o.x) = __floats2half2_rn(acc.x * inv, acc.y * inv);
    *reinterpret_cast<__half2*>(&o.y) = __floats2half2_rn(acc.z * inv, acc.w * inv);
    *reinterpret_cast<uint2*>(&g_back[p][(size_t)n * HD + lane * 4]) = o;
}

// ---------------- decoder ----------------
__global__ void decoder_k(const float* __restrict__ hbase, const float* __restrict__ Wsem,
                          const float* __restrict__ bsem, float* __restrict__ out) {
    int p = blockIdx.y;
    const float* h = hbase + (size_t)p * PSTRIDE;
    float* o = out + (size_t)p * NHIT * NCLASS;
    int warp = (blockIdx.x * blockDim.x + threadIdx.x) >> 5;
    if (warp >= NHIT) return;
    int lane = threadIdx.x & 31;
    int n = warp;
    float hv[4];
    #pragma unroll
    for (int t = 0; t < 4; t++) hv[t] = h[(size_t)n * HD + lane + t * 32];
    #pragma unroll
    for (int c = 0; c < NCLASS; c++) {
        float s = 0.f;
        #pragma unroll
        for (int t = 0; t < 4; t++) s = fmaf(hv[t], Wsem[(lane + t * 32) * NCLASS + c], s);
        #pragma unroll
        for (int d = 16; d > 0; d >>= 1) s += __shfl_down_sync(0xffffffffu, s, d);
        if (lane == 0) o[n * NCLASS + c] = s + bsem[c];
    }
}

// ---------------- host ----------------
extern "C" void kernel_launch(void* const* d_in, const int* in_sizes, int n_in,
                              void* d_out, int out_size) {
    int xi[3], ei[3], ni[3];
    if (in_sizes[1] == 2 * NEDGE) {
        for (int p = 0; p < 3; p++) { xi[p] = 3 * p; ei[p] = 3 * p + 1; ni[p] = 3 * p + 2; }
    } else {
        for (int p = 0; p < 3; p++) { xi[p] = p; ei[p] = 3 + p; ni[p] = 6 + p; }
    }
    const float* x[3]; const int* edge[3]; const int* nexus[3];
    for (int p = 0; p < 3; p++) {
        x[p] = (const float*)d_in[xi[p]];
        edge[p] = (const int*)d_in[ei[p]];
        nexus[p] = (const int*)d_in[ni[p]];
    }
    const float* W_enc  = (const float*)d_in[9];
    const float* b_enc  = (const float*)d_in[10];
    const float* W_msg1 = (const float*)d_in[11];
    const float* b_msg1 = (const float*)d_in[12];
    const float* W_msg2 = (const float*)d_in[13];
    const float* b_msg2 = (const float*)d_in[14];
    const float* W_upd  = (const float*)d_in[15];
    const float* b_upd  = (const float*)d_in[16];
    const float* W_sp   = (const float*)d_in[17];
    const float* b_sp   = (const float*)d_in[18];
    const float* W_nx   = (const float*)d_in[19];
    const float* b_nx   = (const float*)d_in[20];
    const float* W_sem  = (const float*)d_in[21];
    const float* b_sem  = (const float*)d_in[22];

    float *ph, *pwcomb, *pb2c; int* pdeg;
    __half *ph16, *pA, *pB, *pmr, *pspsum, *psp, *pback;
    cudaGetSymbolAddress((void**)&ph, g_h);
    cudaGetSymbolAddress((void**)&ph16, g_h16);
    cudaGetSymbolAddress((void**)&pA, g_A);
    cudaGetSymbolAddress((void**)&pB, g_B);
    cudaGetSymbolAddress((void**)&pmr, g_mr);
    cudaGetSymbolAddress((void**)&pspsum, g_spsum);
    cudaGetSymbolAddress((void**)&psp, g_sp);
    cudaGetSymbolAddress((void**)&pback, g_back);
    cudaGetSymbolAddress((void**)&pwcomb, g_wcomb);
    cudaGetSymbolAddress((void**)&pb2c, g_b2c);
    cudaGetSymbolAddress((void**)&pdeg, g_deg);

    cudaFuncSetAttribute(gemm_mma, cudaFuncAttributeMaxDynamicSharedMemorySize, SM_TOTAL);
    cudaFuncSetAttribute(gemm_dual, cudaFuncAttributeMaxDynamicSharedMemorySize, DU_TOTAL);

    float* h0 = ph;
    float* h1 = ph + (size_t)3 * PSTRIDE;
    __half* h16_0 = ph16;
    __half* h16_1 = ph16 + (size_t)3 * PSTRIDE;

    const int T = 256;
    dim3 gG3((NHIT + 127) / 128, 3);
    dim3 gG1((NHIT + 127) / 128, 1);
    dim3 gW3((NHIT * 32 + T - 1) / T, 3);
    int gW1 = (NSP * 32 + T - 1) / T;
    dim3 gE((NHIT * HD + T - 1) / T, 3);

    // --- CSR build ---
    zero_counts<<<(NHIT + T - 1) / T, T>>>();
    dim3 gCnt((NEDGE + T - 1) / T, 3);
    count_all<<<gCnt, T>>>(edge[0], edge[1], edge[2], nexus[0], nexus[1], nexus[2]);
    scan_excl_all<<<9, 1024>>>();
    fill_all<<<gCnt, T>>>(edge[0], edge[1], edge[2], nexus[0], nexus[1], nexus[2]);

    // --- weight combine + prep (0=W1top 1=W1bot 2=WupdT 3=comb 4=Wsp 5=WnxT 6=WnxB) ---
    combine_w<<<129, 128>>>(W_msg2, W_upd + 128 * 128, b_msg2);
    prep_w<<<224, 256>>>(W_msg1, W_msg1 + 128 * 128, W_upd, pwcomb,
                         W_sp, W_nx, W_nx + 128 * 128);

    // --- encoder ---
    encoder_k<<<gE, T>>>(x[0], x[1], x[2], W_enc, b_enc, h0, h16_0);

    for (int it = 0; it < 3; it++) {
        // planar convolution (msg2 folded into upd via combined weight)
        gemm_dual<<<gG3, T, DU_TOTAL>>>(h16_0, PSTRIDE, 0, 1, pA, pB, NHIT);
        planar_agg<<<gW3, T>>>(b_msg1);
        gemm_mma<<<gG3, T, SM_TOTAL>>>(h16_0, pmr, PSTRIDE, 2, 2, b_upd, pb2c,
                                       pdeg, NHIT, h0, h1, h16_1, NHIT, EPI_RESRELU_DEG);
        // nexus convolution
        nexus_fwd<<<gW1, T>>>(h16_1);
        gemm_mma<<<gG1, T, SM_TOTAL>>>(pspsum, nullptr, 0, 4, 1, b_sp, nullptr,
                                       nullptr, 0, nullptr, nullptr, psp, NSP, EPI_RELU);
        nexus_back<<<gW3, T>>>();
        gemm_mma<<<gG3, T, SM_TOTAL>>>(h16_1, pback, PSTRIDE, 5, 2, b_nx, nullptr,
                                       nullptr, 0, h1, h0, h16_0, NHIT, EPI_RESRELU);
    }

    decoder_k<<<gW3, T>>>(h0, W_sem, b_sem, (float*)d_out);
}

// round 8
// speedup vs baseline: 3.6277x; 1.3085x over previous
#include <cuda_runtime.h>
#include <cuda_fp16.h>
#include <cstdint>

#define NHIT 30000
#define NEDGE 90000
#define NSP 30000
#define HD 128
#define NCLASS 5
#define PSTRIDE (NHIT * HD)

// ---------------- device scratch ----------------
__device__ float g_h[2][3][NHIT * HD];          // fp32 state (residual path)
__device__ __half g_h16[2][3][NHIT * HD];       // fp16 shadow of h (GEMM A operand)
__device__ __half g_A[3][NHIT * HD];
__device__ __half g_B[3][NHIT * HD];
__device__ __half g_mr[3][NHIT * HD];
__device__ __half g_spsum[NSP * HD];
__device__ __half g_sp[NSP * HD];
__device__ __half g_back[3][NHIT * HD];
__device__ float g_wcomb[HD * HD];              // W_msg2 @ W_upd_bottom
__device__ float g_b2c[HD];                     // b_msg2 @ W_upd_bottom

// prepped weights: 7 chunks x {hi,lo} x 2 k-stages x (128n x 64k fp16, swizzled)
__device__ uint4 g_wbuf[7][2][2][1024];

__device__ int g_deg[3][NHIT];
__device__ int g_cf[3][NSP];
__device__ int g_cb[3][NHIT];
__device__ int g_offE[3][NHIT + 1];
__device__ int g_offF[3][NSP + 1];
__device__ int g_offB[3][NHIT + 1];
__device__ int g_csrE[3][NEDGE];
__device__ int g_csrF[3][NSP];
__device__ int g_csrB[3][NSP];
__device__ int g_curE[3][NHIT];
__device__ int g_curF[3][NSP];
__device__ int g_curB[3][NHIT];

enum { EPI_RELU = 1, EPI_RESRELU = 2, EPI_RESRELU_DEG = 4 };

// ---------------- helpers ----------------
__device__ __forceinline__ uint32_t s2u(const void* p) {
    return (uint32_t)__cvta_generic_to_shared(p);
}
__device__ __forceinline__ uint32_t pack2h(float a, float b) {
    __half2 t = __floats2half2_rn(a, b);
    return *reinterpret_cast<uint32_t*>(&t);
}
__device__ __forceinline__ float lopart(float v) {
    return v - __half2float(__float2half(v));
}
__device__ __forceinline__ uint32_t swz(int row, int k) {
    return (uint32_t)(row * 128 + ((((k >> 3) ^ row) & 7) << 4) + (k & 7) * 2);
}
__device__ __forceinline__ void ldsm4(uint32_t* r, uint32_t addr) {
    asm volatile("ldmatrix.sync.aligned.m8n8.x4.shared.b16 {%0,%1,%2,%3}, [%4];"
                 : "=r"(r[0]), "=r"(r[1]), "=r"(r[2]), "=r"(r[3]) : "r"(addr));
}
__device__ __forceinline__ void mma16816(float* c, const uint32_t* a, uint32_t b0, uint32_t b1) {
    asm volatile(
        "mma.sync.aligned.m16n8k16.row.col.f32.f16.f16.f32 "
        "{%0,%1,%2,%3}, {%4,%5,%6,%7}, {%8,%9}, {%0,%1,%2,%3};"
        : "+f"(c[0]), "+f"(c[1]), "+f"(c[2]), "+f"(c[3])
        : "r"(a[0]), "r"(a[1]), "r"(a[2]), "r"(a[3]), "r"(b0), "r"(b1));
}
__device__ __forceinline__ void cpa8(uint32_t dst, const void* src) {
    asm volatile("cp.async.ca.shared.global [%0], [%1], 8;" :: "r"(dst), "l"(src));
}
__device__ __forceinline__ void cpa16(uint32_t dst, const void* src) {
    asm volatile("cp.async.cg.shared.global [%0], [%1], 16;" :: "r"(dst), "l"(src));
}
#define CP_COMMIT() asm volatile("cp.async.commit_group;")
#define CP_WAIT1()  asm volatile("cp.async.wait_group 1;")
#define CP_WAIT0()  asm volatile("cp.async.wait_group 0;")

// gemm_mma: 2 pipeline buffers x [A 16K | BHI 16K | BLO 16K]
#define PB_A 0
#define PB_BHI 16384
#define PB_BLO 32768
#define PB_SZ 49152
#define SM_TOTAL 98304
// gemm_dual: A (both halves) 32K + 2 B-buffers x [BHI 16K | BLO 16K]
#define DU_A 0
#define DU_B 32768
#define DU_BSZ 32768
#define DU_TOTAL 98304

// ---------------- weight combine ----------------
__global__ void combine_w(const float* __restrict__ W2, const float* __restrict__ Wub,
                          const float* __restrict__ b2) {
    int n = threadIdx.x;
    int k = blockIdx.x;
    if (k < 128) {
        float s = 0.f;
        #pragma unroll 8
        for (int j = 0; j < 128; j++) s = fmaf(W2[k * 128 + j], Wub[j * 128 + n], s);
        g_wcomb[k * 128 + n] = s;
    } else {
        float s = 0.f;
        #pragma unroll 8
        for (int j = 0; j < 128; j++) s = fmaf(b2[j], Wub[j * 128 + n], s);
        g_b2c[n] = s;
    }
}

// ---------------- weight prep ----------------
__global__ void prep_w(const float* w0, const float* w1, const float* w2,
                       const float* w3, const float* w4, const float* w5,
                       const float* w6) {
    int id = blockIdx.x * blockDim.x + threadIdx.x;
    if (id >= 7 * 8192) return;
    int c = id >> 13;
    int rem = id & 8191;
    int s = rem >> 12;
    int rem2 = rem & 4095;
    int n = rem2 >> 5;
    int kp = (rem2 & 31) * 2;
    const float* Wc = (c == 0) ? w0 : (c == 1) ? w1 : (c == 2) ? w2 : (c == 3) ? w3
                    : (c == 4) ? w4 : (c == 5) ? w5 : w6;
    float v0 = Wc[(s * 64 + kp) * 128 + n];
    float v1 = Wc[(s * 64 + kp + 1) * 128 + n];
    uint32_t o = swz(n, kp);
    *reinterpret_cast<uint32_t*>((char*)&g_wbuf[c][0][s][0] + o) = pack2h(v0, v1);
    *reinterpret_cast<uint32_t*>((char*)&g_wbuf[c][1][s][0] + o) = pack2h(lopart(v0), lopart(v1));
}

// ---------------- HMMA 2-pass GEMM, cp.async double-buffered ----------------
__global__ __launch_bounds__(256, 2) void gemm_mma(
    const __half* __restrict__ Ah0, const __half* __restrict__ Ah1,
    int sA, int wc0, int nchunks,
    const float* __restrict__ bias, const float* __restrict__ bias2,
    const int* __restrict__ mask, int sMask,
    const float* __restrict__ resid,
    float* __restrict__ outf, __half* __restrict__ outh, int M, int epi)
{
    extern __shared__ char smem[];
    uint32_t sb = s2u(smem);
    int tid = threadIdx.x;
    int wid = tid >> 5, lane = tid & 31;
    int mwarp = wid & 3, nwarp = wid >> 2;
    int row0 = blockIdx.x * 128;
    int pl = blockIdx.y;
    const __half* Ah0p = Ah0 + (size_t)pl * sA;
    const __half* Ah1p = Ah1 ? (Ah1 + (size_t)pl * sA) : nullptr;
    const float* residp = resid ? (resid + (size_t)pl * sA) : nullptr;
    const int* maskp = mask ? (mask + (size_t)pl * sMask) : nullptr;

    float C[2][8][4];
    #pragma unroll
    for (int mt = 0; mt < 2; mt++)
        #pragma unroll
        for (int nt = 0; nt < 8; nt++)
            #pragma unroll
            for (int q = 0; q < 4; q++) C[mt][nt][q] = 0.f;

    int a_row_in16 = (lane & 7) + ((lane >> 3) & 1) * 8;
    int a_kb = (lane >> 4) & 1;
    int b_row_in16 = (lane & 7) + ((lane >> 4) & 1) * 8;
    int b_kb = (lane >> 3) & 1;

    int nst = nchunks * 2;

    auto prefetch = [&](int s) {
        int ch = s >> 1, kh = s & 1;
        const __half* src = ch ? Ah1p : Ah0p;
        uint32_t bb = sb + (uint32_t)((s & 1) * PB_SZ);
        #pragma unroll
        for (int l = 0; l < 8; l++) {
            int i = l * 256 + tid;
            int r = i >> 4, c4 = (i & 15) * 4;
            int row = row0 + r; if (row >= M) row = M - 1;
            cpa8(bb + PB_A + swz(r, c4), &src[(size_t)row * 128 + kh * 64 + c4]);
        }
        const uint4* bh = &g_wbuf[wc0 + ch][0][kh][0];
        const uint4* bl = &g_wbuf[wc0 + ch][1][kh][0];
        #pragma unroll
        for (int l = 0; l < 4; l++) {
            int i = l * 256 + tid;
            cpa16(bb + PB_BHI + (uint32_t)i * 16, bh + i);
            cpa16(bb + PB_BLO + (uint32_t)i * 16, bl + i);
        }
        CP_COMMIT();
    };

    prefetch(0);
    for (int s = 0; s < nst; s++) {
        if (s + 1 < nst) { prefetch(s + 1); CP_WAIT1(); }
        else             { CP_WAIT0(); }
        __syncthreads();
        uint32_t ab = sb + (uint32_t)((s & 1) * PB_SZ);

        #pragma unroll
        for (int k16 = 0; k16 < 4; k16++) {
            uint32_t a[2][4];
            #pragma unroll
            for (int mt = 0; mt < 2; mt++) {
                int row = mwarp * 32 + mt * 16 + a_row_in16;
                uint32_t o = (uint32_t)(row * 128 + ((((k16 * 2 + a_kb) ^ row) & 7) << 4));
                ldsm4(a[mt], ab + PB_A + o);
            }
            #pragma unroll
            for (int ntp = 0; ntp < 4; ntp++) {
                int nrow = nwarp * 64 + ntp * 16 + b_row_in16;
                uint32_t o = (uint32_t)(nrow * 128 + ((((k16 * 2 + b_kb) ^ nrow) & 7) << 4));
                uint32_t bhi[4], blo[4];
                ldsm4(bhi, ab + PB_BHI + o);
                ldsm4(blo, ab + PB_BLO + o);
                #pragma unroll
                for (int half = 0; half < 2; half++) {
                    int nt = ntp * 2 + half;
                    #pragma unroll
                    for (int mt = 0; mt < 2; mt++) {
                        mma16816(C[mt][nt], a[mt], bhi[half * 2], bhi[half * 2 + 1]);
                        mma16816(C[mt][nt], a[mt], blo[half * 2], blo[half * 2 + 1]);
                    }
                }
            }
        }
        __syncthreads();
    }

    int qrow = lane >> 2;
    int qcol = (lane & 3) * 2;
    #pragma unroll
    for (int mt = 0; mt < 2; mt++) {
        #pragma unroll
        for (int half = 0; half < 2; half++) {
            int row = row0 + mwarp * 32 + mt * 16 + qrow + half * 8;
            if (row >= M) continue;
            bool dg = (epi == EPI_RESRELU_DEG) ? (maskp[row] > 0) : false;
            #pragma unroll
            for (int nt = 0; nt < 8; nt++) {
                int col = nwarp * 64 + nt * 8 + qcol;
                float v0 = C[mt][nt][half * 2 + 0];
                float v1 = C[mt][nt][half * 2 + 1];
                float o0, o1;
                if (epi == EPI_RELU) {
                    o0 = fmaxf(v0 + bias[col], 0.f);
                    o1 = fmaxf(v1 + bias[col + 1], 0.f);
                } else {
                    float e0 = v0 + bias[col], e1 = v1 + bias[col + 1];
                    if (epi == EPI_RESRELU_DEG && dg) { e0 += bias2[col]; e1 += bias2[col + 1]; }
                    float2 rr = *reinterpret_cast<const float2*>(&residp[(size_t)row * 128 + col]);
                    o0 = rr.x + fmaxf(e0, 0.f);
                    o1 = rr.y + fmaxf(e1, 0.f);
                }
                if (outf)
                    *reinterpret_cast<float2*>(&outf[(size_t)pl * sA + (size_t)row * 128 + col]) =
                        make_float2(o0, o1);
                if (outh)
                    *reinterpret_cast<__half2*>(&outh[(size_t)pl * sA + (size_t)row * 128 + col]) =
                        __floats2half2_rn(o0, o1);
            }
        }
    }
}

// ---------------- dual-output GEMM, cp.async pipelined B ----------------
__global__ __launch_bounds__(256, 2) void gemm_dual(
    const __half* __restrict__ A, int sA, int wc0, int wc1,
    __half* __restrict__ out0, __half* __restrict__ out1, int M)
{
    extern __shared__ char smem[];
    uint32_t sb = s2u(smem);
    int tid = threadIdx.x;
    int wid = tid >> 5, lane = tid & 31;
    int mwarp = wid & 3, nwarp = wid >> 2;
    int row0 = blockIdx.x * 128;
    int pl = blockIdx.y;
    const __half* Ap = A + (size_t)pl * sA;
    __half* o0 = out0 + (size_t)pl * sA;
    __half* o1 = out1 + (size_t)pl * sA;

    int a_row_in16 = (lane & 7) + ((lane >> 3) & 1) * 8;
    int a_kb = (lane >> 4) & 1;
    int b_row_in16 = (lane & 7) + ((lane >> 4) & 1) * 8;
    int b_kb = (lane >> 3) & 1;
    int qrow = lane >> 2;
    int qcol = (lane & 3) * 2;

    auto prefetchB = [&](int s) {
        int w = s >> 1, kh = s & 1;
        int wc = w ? wc1 : wc0;
        uint32_t bb = sb + DU_B + (uint32_t)((s & 1) * DU_BSZ);
        const uint4* bh = &g_wbuf[wc][0][kh][0];
        const uint4* bl = &g_wbuf[wc][1][kh][0];
        #pragma unroll
        for (int l = 0; l < 4; l++) {
            int i = l * 256 + tid;
            cpa16(bb + (uint32_t)i * 16, bh + i);
            cpa16(bb + 16384 + (uint32_t)i * 16, bl + i);
        }
        CP_COMMIT();
    };

    // A (both 64-k halves) via cp.async, grouped with B stage 0
    #pragma unroll
    for (int l = 0; l < 16; l++) {
        int i = l * 256 + tid;
        int r = i >> 5, c4 = (i & 31) * 4;
        int sh = c4 >> 6, k = c4 & 63;
        int row = row0 + r; if (row >= M) row = M - 1;
        cpa8(sb + DU_A + sh * 16384 + swz(r, k), &Ap[(size_t)row * 128 + c4]);
    }
    prefetchB(0);

    float C[2][8][4];
    for (int s = 0; s < 4; s++) {
        if (s + 1 < 4) { prefetchB(s + 1); CP_WAIT1(); }
        else           { CP_WAIT0(); }
        __syncthreads();

        if ((s & 1) == 0) {
            #pragma unroll
            for (int mt = 0; mt < 2; mt++)
                #pragma unroll
                for (int nt = 0; nt < 8; nt++)
                    #pragma unroll
                    for (int q = 0; q < 4; q++) C[mt][nt][q] = 0.f;
        }

        uint32_t abase = sb + DU_A + (uint32_t)((s & 1) * 16384);
        uint32_t bbase = sb + DU_B + (uint32_t)((s & 1) * DU_BSZ);
        #pragma unroll
        for (int k16 = 0; k16 < 4; k16++) {
            uint32_t a[2][4];
            #pragma unroll
            for (int mt = 0; mt < 2; mt++) {
                int row = mwarp * 32 + mt * 16 + a_row_in16;
                uint32_t o = (uint32_t)(row * 128 + ((((k16 * 2 + a_kb) ^ row) & 7) << 4));
                ldsm4(a[mt], abase + o);
            }
            #pragma unroll
            for (int ntp = 0; ntp < 4; ntp++) {
                int nrow = nwarp * 64 + ntp * 16 + b_row_in16;
                uint32_t o = (uint32_t)(nrow * 128 + ((((k16 * 2 + b_kb) ^ nrow) & 7) << 4));
                uint32_t bhi[4], blo[4];
                ldsm4(bhi, bbase + o);
                ldsm4(blo, bbase + 16384 + o);
                #pragma unroll
                for (int half = 0; half < 2; half++) {
                    int nt = ntp * 2 + half;
                    #pragma unroll
                    for (int mt = 0; mt < 2; mt++) {
                        mma16816(C[mt][nt], a[mt], bhi[half * 2], bhi[half * 2 + 1]);
                        mma16816(C[mt][nt], a[mt], blo[half * 2], blo[half * 2 + 1]);
                    }
                }
            }
        }
        __syncthreads();

        if (s & 1) {
            __half* op = (s >> 1) ? o1 : o0;
            #pragma unroll
            for (int mt = 0; mt < 2; mt++) {
                #pragma unroll
                for (int half = 0; half < 2; half++) {
                    int row = row0 + mwarp * 32 + mt * 16 + qrow + half * 8;
                    if (row >= M) continue;
                    #pragma unroll
                    for (int nt = 0; nt < 8; nt++) {
                        int col = nwarp * 64 + nt * 8 + qcol;
                        *reinterpret_cast<__half2*>(&op[(size_t)row * 128 + col]) =
                            __floats2half2_rn(C[mt][nt][half * 2], C[mt][nt][half * 2 + 1]);
                    }
                }
            }
        }
    }
}

// ---------------- CSR build ----------------
__global__ void zero_counts() {
    int i = blockIdx.x * blockDim.x + threadIdx.x;
    if (i < NHIT) {
        #pragma unroll
        for (int p = 0; p < 3; p++) { g_deg[p][i] = 0; g_cb[p][i] = 0; }
    }
    if (i < NSP) {
        #pragma unroll
        for (int p = 0; p < 3; p++) g_cf[p][i] = 0;
    }
}

__global__ void count_all(const int* __restrict__ e0, const int* __restrict__ e1,
                          const int* __restrict__ e2, const int* __restrict__ n0,
                          const int* __restrict__ n1, const int* __restrict__ n2) {
    int p = blockIdx.y;
    const int* e = (p == 0) ? e0 : (p == 1) ? e1 : e2;
    const int* nx = (p == 0) ? n0 : (p == 1) ? n1 : n2;
    int i = blockIdx.x * blockDim.x + threadIdx.x;
    if (i < NEDGE) atomicAdd(&g_deg[p][e[NEDGE + i]], 1);
    if (i < NSP) {
        atomicAdd(&g_cf[p][nx[NSP + i]], 1);
        atomicAdd(&g_cb[p][nx[i]], 1);
    }
}

__global__ void scan_excl_all() {
    int sel = blockIdx.x / 3, p = blockIdx.x % 3;
    const int* in; int* out; int* cur; int n;
    if (sel == 0)      { in = g_deg[p]; out = g_offE[p]; cur = g_curE[p]; n = NHIT; }
    else if (sel == 1) { in = g_cf[p];  out = g_offF[p]; cur = g_curF[p]; n = NSP; }
    else               { in = g_cb[p];  out = g_offB[p]; cur = g_curB[p]; n = NHIT; }
    __shared__ int wsum[32];
    __shared__ int carry;
    int tid = threadIdx.x;
    if (tid == 0) carry = 0;
    __syncthreads();
    for (int base = 0; base < n; base += 1024) {
        int i = base + tid;
        int v = (i < n) ? in[i] : 0;
        int x = v;
        #pragma unroll
        for (int d = 1; d < 32; d <<= 1) {
            int y = __shfl_up_sync(0xffffffffu, x, d);
            if ((tid & 31) >= d) x += y;
        }
        if ((tid & 31) == 31) wsum[tid >> 5] = x;
        __syncthreads();
        if (tid < 32) {
            int s = wsum[tid];
            #pragma unroll
            for (int d = 1; d < 32; d <<= 1) {
                int y = __shfl_up_sync(0xffffffffu, s, d);
                if (tid >= d) s += y;
            }
            wsum[tid] = s;
        }
        __syncthreads();
        int woff = (tid >= 32) ? wsum[(tid >> 5) - 1] : 0;
        int incl = carry + woff + x;
        if (i < n) { out[i] = incl - v; cur[i] = incl - v; }
        __syncthreads();
        if (tid == 1023) carry = incl;
        __syncthreads();
    }
    if (tid == 0) out[n] = carry;
}

__global__ void fill_all(const int* __restrict__ e0, const int* __restrict__ e1,
                         const int* __restrict__ e2, const int* __restrict__ n0,
                         const int* __restrict__ n1, const int* __restrict__ n2) {
    int p = blockIdx.y;
    const int* e = (p == 0) ? e0 : (p == 1) ? e1 : e2;
    const int* nx = (p == 0) ? n0 : (p == 1) ? n1 : n2;
    int i = blockIdx.x * blockDim.x + threadIdx.x;
    if (i < NEDGE) {
        int dst = e[NEDGE + i];
        g_csrE[p][atomicAdd(&g_curE[p][dst], 1)] = e[i];
    }
    if (i < NSP) {
        int s = nx[NSP + i];
        g_csrF[p][atomicAdd(&g_curF[p][s], 1)] = nx[i];
        int h = nx[i];
        g_csrB[p][atomicAdd(&g_curB[p][h], 1)] = nx[NSP + i];
    }
}

// ---------------- encoder ----------------
__global__ void encoder_k(const float* __restrict__ x0, const float* __restrict__ x1,
                          const float* __restrict__ x2, const float* __restrict__ W,
                          const float* __restrict__ b, float* __restrict__ hbase,
                          __half* __restrict__ h16base) {
    int p = blockIdx.y;
    const float* x = (p == 0) ? x0 : (p == 1) ? x1 : x2;
    int idx = blockIdx.x * blockDim.x + threadIdx.x;
    if (idx >= NHIT * HD) return;
    int n = idx >> 7, j = idx & 127;
    float acc = b[j];
    #pragma unroll
    for (int k = 0; k < 4; k++) acc = fmaf(x[n * 4 + k], W[k * HD + j], acc);
    acc = fmaxf(acc, 0.f);
    hbase[(size_t)p * PSTRIDE + idx] = acc;
    h16base[(size_t)p * PSTRIDE + idx] = __float2half(acc);
}

// ---------------- planar edge aggregation ----------------
__global__ void planar_agg(const float* __restrict__ b1) {
    int p = blockIdx.y;
    int warp = (blockIdx.x * blockDim.x + threadIdx.x) >> 5;
    if (warp >= NHIT) return;
    int lane = threadIdx.x & 31;
    int n = warp;
    uint2 ar = *reinterpret_cast<const uint2*>(&g_A[p][(size_t)n * HD + lane * 4]);
    float2 a01 = __half22float2(*reinterpret_cast<__half2*>(&ar.x));
    float2 a23 = __half22float2(*reinterpret_cast<__half2*>(&ar.y));
    float4 bb = *reinterpret_cast<const float4*>(&b1[lane * 4]);
    int s = g_offE[p][n], e = g_offE[p][n + 1];
    float4 acc = make_float4(0.f, 0.f, 0.f, 0.f);
    for (int i = s; i < e; i++) {
        int src = g_csrE[p][i];
        uint2 br = *reinterpret_cast<const uint2*>(&g_B[p][(size_t)src * HD + lane * 4]);
        float2 b01 = __half22float2(*reinterpret_cast<__half2*>(&br.x));
        float2 b23 = __half22float2(*reinterpret_cast<__half2*>(&br.y));
        acc.x += fmaxf(a01.x + b01.x + bb.x, 0.f);
        acc.y += fmaxf(a01.y + b01.y + bb.y, 0.f);
        acc.z += fmaxf(a23.x + b23.x + bb.z, 0.f);
        acc.w += fmaxf(a23.y + b23.y + bb.w, 0.f);
    }
    float inv = (e > s) ? 1.f / (float)(e - s) : 0.f;
    uint2 o;
    *reinterpret_cast<__half2*>(&o.x) = __floats2half2_rn(acc.x * inv, acc.y * inv);
    *reinterpret_cast<__half2*>(&o.y) = __floats2half2_rn(acc.z * inv, acc.w * inv);
    *reinterpret_cast<uint2*>(&g_mr[p][(size_t)n * HD + lane * 4]) = o;
}

// ---------------- nexus forward ----------------
__global__ void nexus_fwd(const __half* __restrict__ h16base) {
    int warp = (blockIdx.x * blockDim.x + threadIdx.x) >> 5;
    if (warp >= NSP) return;
    int lane = threadIdx.x & 31;
    int s = warp;
    float4 tot = make_float4(0.f, 0.f, 0.f, 0.f);
    #pragma unroll
    for (int p = 0; p < 3; p++) {
        const __half* h = h16base + (size_t)p * PSTRIDE;
        int st = g_offF[p][s], en = g_offF[p][s + 1];
        float4 acc = make_float4(0.f, 0.f, 0.f, 0.f);
        for (int i = st; i < en; i++) {
            int hit = g_csrF[p][i];
            uint2 vr = *reinterpret_cast<const uint2*>(&h[(size_t)hit * HD + lane * 4]);
            float2 v01 = __half22float2(*reinterpret_cast<__half2*>(&vr.x));
            float2 v23 = __half22float2(*reinterpret_cast<__half2*>(&vr.y));
            acc.x += v01.x; acc.y += v01.y; acc.z += v23.x; acc.w += v23.y;
        }
        if (en > st) {
            float inv = 1.f / (float)(en - st);
            tot.x += acc.x * inv; tot.y += acc.y * inv;
            tot.z += acc.z * inv; tot.w += acc.w * inv;
        }
    }
    uint2 o;
    *reinterpret_cast<__half2*>(&o.x) = __floats2half2_rn(tot.x, tot.y);
    *reinterpret_cast<__half2*>(&o.y) = __floats2half2_rn(tot.z, tot.w);
    *reinterpret_cast<uint2*>(&g_spsum[(size_t)s * HD + lane * 4]) = o;
}

// ---------------- nexus backward ----------------
__global__ void nexus_back() {
    int p = blockIdx.y;
    int warp = (blockIdx.x * blockDim.x + threadIdx.x) >> 5;
    if (warp >= NHIT) return;
    int lane = threadIdx.x & 31;
    int n = warp;
    int st = g_offB[p][n], en = g_offB[p][n + 1];
    float4 acc = make_float4(0.f, 0.f, 0.f, 0.f);
    for (int i = st; i < en; i++) {
        int spi = g_csrB[p][i];
        uint2 vr = *reinterpret_cast<const uint2*>(&g_sp[(size_t)spi * HD + lane * 4]);
        float2 v01 = __half22float2(*reinterpret_cast<__half2*>(&vr.x));
        float2 v23 = __half22float2(*reinterpret_cast<__half2*>(&vr.y));
        acc.x += v01.x; acc.y += v01.y; acc.z += v23.x; acc.w += v23.y;
    }
    float inv = (en > st) ? 1.f / (float)(en - st) : 0.f;
    uint2 o;
    *reinterpret_cast<__half2*>(&o.x) = __floats2half2_rn(acc.x * inv, acc.y * inv);
    *reinterpret_cast<__half2*>(&o.y) = __floats2half2_rn(acc.z * inv, acc.w * inv);
    *reinterpret_cast<uint2*>(&g_back[p][(size_t)n * HD + lane * 4]) = o;
}

// ---------------- decoder ----------------
__global__ void decoder_k(const float* __restrict__ hbase, const float* __restrict__ Wsem,
                          const float* __restrict__ bsem, float* __restrict__ out) {
    int p = blockIdx.y;
    const float* h = hbase + (size_t)p * PSTRIDE;
    float* o = out + (size_t)p * NHIT * NCLASS;
    int warp = (blockIdx.x * blockDim.x + threadIdx.x) >> 5;
    if (warp >= NHIT) return;
    int lane = threadIdx.x & 31;
    int n = warp;
    float hv[4];
    #pragma unroll
    for (int t = 0; t < 4; t++) hv[t] = h[(size_t)n * HD + lane + t * 32];
    #pragma unroll
    for (int c = 0; c < NCLASS; c++) {
        float s = 0.f;
        #pragma unroll
        for (int t = 0; t < 4; t++) s = fmaf(hv[t], Wsem[(lane + t * 32) * NCLASS + c], s);
        #pragma unroll
        for (int d = 16; d > 0; d >>= 1) s += __shfl_down_sync(0xffffffffu, s, d);
        if (lane == 0) o[n * NCLASS + c] = s + bsem[c];
    }
}

// ---------------- host ----------------
extern "C" void kernel_launch(void* const* d_in, const int* in_sizes, int n_in,
                              void* d_out, int out_size) {
    int xi[3], ei[3], ni[3];
    if (in_sizes[1] == 2 * NEDGE) {
        for (int p = 0; p < 3; p++) { xi[p] = 3 * p; ei[p] = 3 * p + 1; ni[p] = 3 * p + 2; }
    } else {
        for (int p = 0; p < 3; p++) { xi[p] = p; ei[p] = 3 + p; ni[p] = 6 + p; }
    }
    const float* x[3]; const int* edge[3]; const int* nexus[3];
    for (int p = 0; p < 3; p++) {
        x[p] = (const float*)d_in[xi[p]];
        edge[p] = (const int*)d_in[ei[p]];
        nexus[p] = (const int*)d_in[ni[p]];
    }
    const float* W_enc  = (const float*)d_in[9];
    const float* b_enc  = (const float*)d_in[10];
    const float* W_msg1 = (const float*)d_in[11];
    const float* b_msg1 = (const float*)d_in[12];
    const float* W_msg2 = (const float*)d_in[13];
    const float* b_msg2 = (const float*)d_in[14];
    const float* W_upd  = (const float*)d_in[15];
    const float* b_upd  = (const float*)d_in[16];
    const float* W_sp   = (const float*)d_in[17];
    const float* b_sp   = (const float*)d_in[18];
    const float* W_nx   = (const float*)d_in[19];
    const float* b_nx   = (const float*)d_in[20];
    const float* W_sem  = (const float*)d_in[21];
    const float* b_sem  = (const float*)d_in[22];

    float *ph, *pwcomb, *pb2c; int* pdeg;
    __half *ph16, *pA, *pB, *pmr, *pspsum, *psp, *pback;
    cudaGetSymbolAddress((void**)&ph, g_h);
    cudaGetSymbolAddress((void**)&ph16, g_h16);
    cudaGetSymbolAddress((void**)&pA, g_A);
    cudaGetSymbolAddress((void**)&pB, g_B);
    cudaGetSymbolAddress((void**)&pmr, g_mr);
    cudaGetSymbolAddress((void**)&pspsum, g_spsum);
    cudaGetSymbolAddress((void**)&psp, g_sp);
    cudaGetSymbolAddress((void**)&pback, g_back);
    cudaGetSymbolAddress((void**)&pwcomb, g_wcomb);
    cudaGetSymbolAddress((void**)&pb2c, g_b2c);
    cudaGetSymbolAddress((void**)&pdeg, g_deg);

    cudaFuncSetAttribute(gemm_mma, cudaFuncAttributeMaxDynamicSharedMemorySize, SM_TOTAL);
    cudaFuncSetAttribute(gemm_dual, cudaFuncAttributeMaxDynamicSharedMemorySize, DU_TOTAL);

    float* h0 = ph;
    float* h1 = ph + (size_t)3 * PSTRIDE;
    __half* h16_0 = ph16;
    __half* h16_1 = ph16 + (size_t)3 * PSTRIDE;

    const int T = 256;
    dim3 gG3((NHIT + 127) / 128, 3);
    dim3 gG1((NHIT + 127) / 128, 1);
    dim3 gW3((NHIT * 32 + T - 1) / T, 3);
    int gW1 = (NSP * 32 + T - 1) / T;
    dim3 gE((NHIT * HD + T - 1) / T, 3);

    // --- CSR build ---
    zero_counts<<<(NHIT + T - 1) / T, T>>>();
    dim3 gCnt((NEDGE + T - 1) / T, 3);
    count_all<<<gCnt, T>>>(edge[0], edge[1], edge[2], nexus[0], nexus[1], nexus[2]);
    scan_excl_all<<<9, 1024>>>();
    fill_all<<<gCnt, T>>>(edge[0], edge[1], edge[2], nexus[0], nexus[1], nexus[2]);

    // --- weight combine + prep (0=W1top 1=W1bot 2=WupdT 3=comb 4=Wsp 5=WnxT 6=WnxB) ---
    combine_w<<<129, 128>>>(W_msg2, W_upd + 128 * 128, b_msg2);
    prep_w<<<224, 256>>>(W_msg1, W_msg1 + 128 * 128, W_upd, pwcomb,
                         W_sp, W_nx, W_nx + 128 * 128);

    // --- encoder ---
    encoder_k<<<gE, T>>>(x[0], x[1], x[2], W_enc, b_enc, h0, h16_0);

    for (int it = 0; it < 3; it++) {
        gemm_dual<<<gG3, T, DU_TOTAL>>>(h16_0, PSTRIDE, 0, 1, pA, pB, NHIT);
        planar_agg<<<gW3, T>>>(b_msg1);
        gemm_mma<<<gG3, T, SM_TOTAL>>>(h16_0, pmr, PSTRIDE, 2, 2, b_upd, pb2c,
                                       pdeg, NHIT, h0, h1, h16_1, NHIT, EPI_RESRELU_DEG);
        nexus_fwd<<<gW1, T>>>(h16_1);
        gemm_mma<<<gG1, T, SM_TOTAL>>>(pspsum, nullptr, 0, 4, 1, b_sp, nullptr,
                                       nullptr, 0, nullptr, nullptr, psp, NSP, EPI_RELU);
        nexus_back<<<gW3, T>>>();
        gemm_mma<<<gG3, T, SM_TOTAL>>>(h16_1, pback, PSTRIDE, 5, 2, b_nx, nullptr,
                                       nullptr, 0, h1, h0, h16_0, NHIT, EPI_RESRELU);
    }

    decoder_k<<<gW3, T>>>(h0, W_sem, b_sem, (float*)d_out);
}